// round 14
// baseline (speedup 1.0000x reference)
#include <cuda_runtime.h>
#include <math.h>
#include <stdint.h>

#define B_    8
#define N_    1024
#define DIM_  768
#define H_    8
#define HD_   96
#define E_    24
#define NT    (B_*N_)      /* 8192 tokens */
#define NA    (NT*H_)      /* 65536 assignments */
#define SCALE_ 0.10206207261596575f  /* 96^-0.5 */

/* k-group permutation: word for logical index d lives at KPERM(d).
   Within each 8-word group, fragment pairs (i, i+4) land adjacent (2i, 2i+1). */
#define KPERM(d) (((d) & ~7) | (((d) & 3) << 1) | (((d) >> 2) & 1))

/* ------------------------- scratch (device globals) ------------------------- */
__device__ float    g_gate[NA];
__device__ float    g_me[E_];        /* zero-init; aux re-zeroes each run */
__device__ float    g_z;
__device__ int      g_ecount[E_];
__device__ int      g_elist[E_*NA];
__device__ uint32_t g_kt[NT*HD_];                 /* k tf32, k-permuted          */
__device__ uint32_t g_vtT[NT*HD_];                /* v tf32 transposed [b][d][j] */
__device__ uint32_t g_qt[(size_t)NA*HD_];         /* q*scale tf32, k-permuted    */
__device__ uint32_t g_ot[(size_t)NA*HD_];         /* gate*o tf32, k-permuted     */
__device__ uint32_t g_xt[(size_t)NT*DIM_];        /* x tf32, k-permuted          */
__device__ uint32_t g_w1t[(size_t)E_*HD_*DIM_];   /* W1^T [e][c][k], permuted    */
__device__ uint32_t g_w2t[(size_t)E_*DIM_*HD_];   /* W2^T [e][c][k], permuted    */

__device__ __forceinline__ uint32_t f2tf32(float f) {
    uint32_t r;
    asm("cvt.rna.tf32.f32 %0, %1;" : "=r"(r) : "f"(f));
    return r;
}

__device__ __forceinline__ void mma_tf32(float* d, const uint32_t* a, const uint32_t* b) {
    asm("mma.sync.aligned.m16n8k8.row.col.f32.tf32.tf32.f32 "
        "{%0,%1,%2,%3}, {%4,%5,%6,%7}, {%8,%9}, {%0,%1,%2,%3};"
        : "+f"(d[0]), "+f"(d[1]), "+f"(d[2]), "+f"(d[3])
        : "r"(a[0]), "r"(a[1]), "r"(a[2]), "r"(a[3]), "r"(b[0]), "r"(b[1]));
}

__device__ __forceinline__ void red_add_v2(float* addr, float a, float b) {
    asm volatile("red.global.add.v2.f32 [%0], {%1, %2};"
                 :: "l"(addr), "f"(a), "f"(b) : "memory");
}

__device__ __forceinline__ void cp_async16(uint32_t dst_smem, const void* src) {
    asm volatile("cp.async.cg.shared.global [%0], [%1], 16;"
                 :: "r"(dst_smem), "l"(src));
}
__device__ __forceinline__ void cp_commit() {
    asm volatile("cp.async.commit_group;");
}
template<int N> __device__ __forceinline__ void cp_wait() {
    asm volatile("cp.async.wait_group %0;" :: "n"(N));
}

/* ===== prep: gate+preconvert (0-1023) | kv (1024-1279) | zero (1280-1535) ===== */
__global__ void prep_kernel(const float* __restrict__ x,
                            const float* __restrict__ Wg,
                            const float* __restrict__ W1,
                            const float* __restrict__ W2,
                            const float* __restrict__ Wkv,
                            const float* __restrict__ bkv,
                            const int*   __restrict__ task_p,
                            float* __restrict__ out, int out_size) {
    __shared__ float sbuf[4352];
    __shared__ float sme[E_];
    __shared__ float szv;
    __shared__ int   scnt[E_];
    __shared__ int   sbase[E_];
    int bx  = blockIdx.x;
    int tid = threadIdx.x;

    if (bx < 1024) {
        /* ------------------- gating ------------------- */
        int warp = tid >> 5, lane = tid & 31;
        int t = bx * 8 + warp;
        if (tid < E_) { sme[tid] = 0.f; scnt[tid] = 0; }
        if (tid == 0) szv = 0.f;
        __syncthreads();

        int task = *task_p;
        const float* wg = Wg + (size_t)task * DIM_ * E_;
        const float* xr = x + (size_t)t * DIM_;

        float acc = 0.f;
        if (lane < E_) {
            #pragma unroll 4
            for (int d = 0; d < DIM_; d++) acc += xr[d] * wg[d * E_ + lane];
        }
        float logit = (lane < E_) ? acc : -1e30f;

        float m = logit;
        #pragma unroll
        for (int o = 16; o >= 1; o >>= 1) m = fmaxf(m, __shfl_xor_sync(0xffffffffu, m, o));
        float p = (lane < E_) ? expf(logit - m) : 0.f;
        float s = p;
        #pragma unroll
        for (int o = 16; o >= 1; o >>= 1) s += __shfl_xor_sync(0xffffffffu, s, o);
        float prob = p / s;
        float lse = m + logf(s);
        if (lane == 0) atomicAdd(&szv, lse * lse);
        if (lane < E_) atomicAdd(&sme[lane], prob);

        float val = (lane < E_) ? prob : -1.f;
        float sel_g = 0.f; int sel_e = 0;
        #pragma unroll
        for (int it = 0; it < H_; it++) {
            float mm = val;
            #pragma unroll
            for (int o = 16; o >= 1; o >>= 1)
                mm = fmaxf(mm, __shfl_xor_sync(0xffffffffu, mm, o));
            unsigned msk = __ballot_sync(0xffffffffu, val == mm);
            int src = __ffs(msk) - 1;
            if (lane == src) val = -1.f;
            if (lane == it) { sel_e = src; sel_g = mm; }
        }
        float gv = (lane < H_) ? sel_g : 0.f;
        #pragma unroll
        for (int o = 16; o >= 1; o >>= 1) gv += __shfl_xor_sync(0xffffffffu, gv, o);
        float denom = gv + 1e-6f;

        int pos = 0;
        if (lane < H_) pos = atomicAdd(&scnt[sel_e], 1);
        __syncthreads();
        if (tid < E_) sbase[tid] = atomicAdd(&g_ecount[tid], scnt[tid]);
        __syncthreads();
        if (lane < H_) {
            int a = t * H_ + lane;
            g_gate[a] = sel_g / denom;
            g_elist[sel_e * NA + sbase[sel_e] + pos] = a;
        }
        if (tid < E_) atomicAdd(&g_me[tid], sme[tid]);
        if (tid == 0) atomicAdd(&g_z, szv);

        /* ---- pre-convert x -> g_xt (tf32, k-permuted per 8-group) ---- */
        {
            const float4* xin = (const float4*)x;
            uint4* xout = (uint4*)g_xt;
            int gbase = bx * 768;              /* 8-word groups per block */
            for (int i = tid; i < 768; i += 256) {
                int gi = gbase + i;
                float4 in0 = xin[2 * gi], in1 = xin[2 * gi + 1];
                uint4 lo, hi;
                lo.x = f2tf32(in0.x); lo.y = f2tf32(in1.x);
                lo.z = f2tf32(in0.y); lo.w = f2tf32(in1.y);
                hi.x = f2tf32(in0.z); hi.y = f2tf32(in1.z);
                hi.z = f2tf32(in0.w); hi.w = f2tf32(in1.w);
                xout[2 * gi]     = lo;
                xout[2 * gi + 1] = hi;
            }
        }

        /* ---- W1 -> g_w1t [e][c][k] permuted (1728 tiles) ---- */
        float (*tile)[33] = (float(*)[33])sbuf;
        int ty = tid >> 5, tx8 = tid & 31;
        int kp = KPERM(tx8);
        for (int tix = bx; tix < 1728; tix += 1024) {
            int e  = tix / 72;
            int rem = tix % 72;
            int kt = rem / 3, ct = rem % 3;
            __syncthreads();
            for (int r = ty; r < 32; r += 8)
                tile[r][tx8] = W1[((size_t)e * DIM_ + kt * 32 + r) * HD_ + ct * 32 + tx8];
            __syncthreads();
            for (int r = ty; r < 32; r += 8)
                g_w1t[((size_t)e * HD_ + ct * 32 + r) * DIM_ + kt * 32 + kp] =
                    f2tf32(tile[tx8][r]);
        }

        /* ---- W2 -> g_w2t [e][c][k] permuted (1728 tiles; W2 is [e][96][768]) ---- */
        for (int tix = bx; tix < 1728; tix += 1024) {
            int e  = tix / 72;
            int rem = tix % 72;
            int kt = rem / 24, ct = rem % 24;
            __syncthreads();
            for (int r = ty; r < 32; r += 8)
                tile[r][tx8] = W2[((size_t)e * HD_ + kt * 32 + r) * DIM_ + ct * 32 + tx8];
            __syncthreads();
            for (int r = ty; r < 32; r += 8)
                g_w2t[((size_t)e * DIM_ + ct * 32 + r) * HD_ + kt * 32 + kp] =
                    f2tf32(tile[tx8][r]);
        }
    } else if (bx < 1280) {
        /* ---- kv projection: 64 rows x 96 cols per block; two 48-col passes ----
           outputs: k -> g_kt (k-permuted), v -> g_vtT [b][d][j] (j-permuted)   */
        float (*xsT)[68] = (float(*)[68])sbuf;            /* [32][68] = 2176 */
        float (*ws)[52]  = (float(*)[52])(sbuf + 32 * 68); /* [32][52] = 1664 */
        int i = bx - 1024;                 /* 0..255 */
        int r0 = (i & 127) * 64;           /* 128 row-tiles */
        int c0 = (i >> 7) * 96;            /* 0 = k cols, 96 = v cols */
        int ty = tid >> 4, tx = tid & 15;  /* 16x16 threads: 4 rows x 3 cols each */

        for (int half = 0; half < 2; half++) {
            int ch0 = c0 + half * 48;
            float acc[4][3] = {};
            for (int k0 = 0; k0 < DIM_; k0 += 32) {
                __syncthreads();
                for (int ii = tid; ii < 64 * 32; ii += 256) {
                    int r = ii >> 5, k = ii & 31;
                    xsT[k][r] = x[(size_t)(r0 + r) * DIM_ + k0 + k];
                }
                for (int ii = tid; ii < 32 * 48; ii += 256) {
                    int k = ii / 48, c = ii % 48;
                    ws[k][c] = Wkv[(size_t)(k0 + k) * (2 * HD_) + ch0 + c];
                }
                __syncthreads();
                #pragma unroll
                for (int k = 0; k < 32; k++) {
                    float4 a4 = *(const float4*)&xsT[k][ty * 4];
                    float av[4] = {a4.x, a4.y, a4.z, a4.w};
                    float bv[3];
                    #pragma unroll
                    for (int j = 0; j < 3; j++) bv[j] = ws[k][tx + 16 * j];
                    #pragma unroll
                    for (int ri = 0; ri < 4; ri++)
                        #pragma unroll
                        for (int cj = 0; cj < 3; cj++)
                            acc[ri][cj] += av[ri] * bv[cj];
                }
            }
            #pragma unroll
            for (int ri = 0; ri < 4; ri++) {
                int r = r0 + ty * 4 + ri;
                #pragma unroll
                for (int cj = 0; cj < 3; cj++) {
                    int c = ch0 + tx + 16 * cj;
                    uint32_t v = f2tf32(acc[ri][cj] + bkv[c]);
                    if (c < HD_) {
                        g_kt[(size_t)r * HD_ + KPERM(c)] = v;
                    } else {
                        int d = c - HD_;
                        int bb = r >> 10, n = r & (N_ - 1);
                        g_vtT[((size_t)bb * HD_ + d) * N_ + (n & ~7) +
                              (KPERM(n) & 7)] = v;
                    }
                }
            }
        }
    } else {
        /* ------------------- zero output ------------------- */
        int zb = bx - 1280;                /* 0..255 */
        float4* o4 = (float4*)out;
        const int n4 = NT * DIM_ / 4;
        for (int i = zb * 256 + tid; i < n4; i += 256 * 256)
            o4[i] = make_float4(0.f, 0.f, 0.f, 0.f);
        for (int i = NT * DIM_ + zb * 256 + tid; i < out_size; i += 256 * 256)
            out[i] = 0.f;
    }
}

/* ------- grouped q projection: cp.async dbuf, LDS.64 fragments -------------- */
#define Q_SMEM_WORDS (2*128*36 + 2*96*36)
__global__ void __launch_bounds__(256) q_tc_kernel() {
    int e = blockIdx.y;
    int count = g_ecount[e];
    int base = blockIdx.x * 128;
    if (base >= count) return;

    extern __shared__ uint32_t qsm[];
    uint32_t* xs = qsm;
    uint32_t* ws = qsm + 2 * 128 * 36;
    __shared__ int s_a[128];
    int tid = threadIdx.x;
    if (tid < 128) {
        int idx = base + tid; if (idx >= count) idx = count - 1;
        s_a[tid] = g_elist[e * NA + idx];
    }
    __syncthreads();

    uint32_t xs_smem = (uint32_t)__cvta_generic_to_shared(xs);
    uint32_t ws_smem = (uint32_t)__cvta_generic_to_shared(ws);
    const uint32_t* w1t = g_w1t + (size_t)e * HD_ * DIM_;

    int wid = tid >> 5, lane = tid & 31;
    int g = lane >> 2, tig = lane & 3;
    int row_a0 = wid * 16 + g, row_a1 = row_a0 + 8;

    float acc[12][4];
    #pragma unroll
    for (int nn = 0; nn < 12; nn++)
        #pragma unroll
        for (int r = 0; r < 4; r++) acc[nn][r] = 0.f;

    auto fill = [&](int bi, int k0) {
        uint32_t xb = xs_smem + bi * (128 * 36 * 4);
        uint32_t wb = ws_smem + bi * (96 * 36 * 4);
        #pragma unroll
        for (int j = 0; j < 4; j++) {
            int item = tid + 256 * j;
            int r = item >> 3, seg = item & 7;
            int tok = s_a[r] >> 3;
            cp_async16(xb + (r * 36 + seg * 4) * 4,
                       g_xt + (size_t)tok * DIM_ + k0 + seg * 4);
        }
        #pragma unroll
        for (int j = 0; j < 3; j++) {
            int item = tid + 256 * j;
            int c = item >> 3, seg = item & 7;
            cp_async16(wb + (c * 36 + seg * 4) * 4,
                       w1t + (size_t)c * DIM_ + k0 + seg * 4);
        }
        cp_commit();
    };

    fill(0, 0);
    for (int c = 0; c < 24; c++) {
        if (c < 23) fill((c + 1) & 1, (c + 1) * 32);
        if (c < 23) cp_wait<1>(); else cp_wait<0>();
        __syncthreads();
        uint32_t* xsb = xs + (c & 1) * 128 * 36;
        uint32_t* wsb = ws + (c & 1) * 96 * 36;
        #pragma unroll
        for (int kk = 0; kk < 4; kk++) {
            uint32_t a[4];
            uint2 xa0 = *(const uint2*)&xsb[row_a0 * 36 + kk * 8 + 2 * tig];
            uint2 xa1 = *(const uint2*)&xsb[row_a1 * 36 + kk * 8 + 2 * tig];
            a[0] = xa0.x; a[2] = xa0.y;
            a[1] = xa1.x; a[3] = xa1.y;
            #pragma unroll
            for (int nn = 0; nn < 12; nn++) {
                uint2 wb_ = *(const uint2*)&wsb[(nn * 8 + g) * 36 + kk * 8 + 2 * tig];
                uint32_t bb[2] = {wb_.x, wb_.y};
                mma_tf32(acc[nn], a, bb);
            }
        }
        __syncthreads();
    }

    bool ok0 = (base + row_a0 < count), ok1 = (base + row_a1 < count);
    int a0 = s_a[row_a0], a1 = s_a[row_a1];
    #pragma unroll
    for (int nn = 0; nn < 12; nn++) {
        int c = nn * 8 + tig * 2;
        if (ok0) {
            g_qt[(size_t)a0 * HD_ + KPERM(c)]     = f2tf32(acc[nn][0] * SCALE_);
            g_qt[(size_t)a0 * HD_ + KPERM(c + 1)] = f2tf32(acc[nn][1] * SCALE_);
        }
        if (ok1) {
            g_qt[(size_t)a1 * HD_ + KPERM(c)]     = f2tf32(acc[nn][2] * SCALE_);
            g_qt[(size_t)a1 * HD_ + KPERM(c + 1)] = f2tf32(acc[nn][3] * SCALE_);
        }
    }
}

/* ------- fused flash attention: cp.async dbuf, LDS.64 fragments ------------- */
#define QS_STRIDE 100
#define KS_STRIDE 100
#define VS_STRIDE 68
#define PS_STRIDE 68
#define ATTN_SMEM_WORDS (128*QS_STRIDE + 2*64*KS_STRIDE + 2*96*VS_STRIDE + 8*16*PS_STRIDE)

__global__ void __launch_bounds__(256, 1) attn_tc_kernel() {
    extern __shared__ uint32_t smu[];
    uint32_t* qs = smu;                                    /* [128][100]   */
    uint32_t* ks = qs + 128 * QS_STRIDE;                   /* [2][64][100] */
    uint32_t* vs = ks + 2 * 64 * KS_STRIDE;                /* [2][96][68]  */
    uint32_t* ps = vs + 2 * 96 * VS_STRIDE;                /* [8][16][68]  */

    int it = blockIdx.x, bh = blockIdx.y;
    int b = bh >> 3, h = bh & 7;
    int i0 = it * 128;
    int tid  = threadIdx.x;
    int wid  = tid >> 5;
    int lane = tid & 31;
    int g    = lane >> 2;
    int tig  = lane & 3;
    uint32_t* pw = ps + wid * 16 * PS_STRIDE;

    uint32_t qs_s = (uint32_t)__cvta_generic_to_shared(qs);
    uint32_t ks_s = (uint32_t)__cvta_generic_to_shared(ks);
    uint32_t vs_s = (uint32_t)__cvta_generic_to_shared(vs);

    #pragma unroll
    for (int j = 0; j < 12; j++) {
        int item = tid + 256 * j;
        int r = item / 24, seg = item % 24;
        cp_async16(qs_s + (r * QS_STRIDE + seg * 4) * 4,
                   g_qt + ((size_t)(b * N_ + i0 + r) * H_ + h) * HD_ + seg * 4);
    }
    cp_commit();

    auto fill_kv = [&](int bi, int jt) {
        int j0 = jt * 64;
        uint32_t kb = ks_s + bi * (64 * KS_STRIDE * 4);
        uint32_t vb = vs_s + bi * (96 * VS_STRIDE * 4);
        #pragma unroll
        for (int j = 0; j < 6; j++) {          /* K: 64 rows x 24 segs */
            int item = tid + 256 * j;
            int r = item / 24, seg = item % 24;
            cp_async16(kb + (r * KS_STRIDE + seg * 4) * 4,
                       g_kt + (size_t)(b * N_ + j0 + r) * HD_ + seg * 4);
        }
        #pragma unroll
        for (int j = 0; j < 6; j++) {          /* V^T: 96 rows x 16 segs */
            int item = tid + 256 * j;
            int d = item >> 4, seg = item & 15;
            cp_async16(vb + (d * VS_STRIDE + seg * 4) * 4,
                       g_vtT + ((size_t)b * HD_ + d) * N_ + j0 + seg * 4);
        }
        cp_commit();
    };
    fill_kv(0, 0);

    float m0 = -1e30f, m1 = -1e30f, l0 = 0.f, l1 = 0.f;
    float o_acc[12][4];
    #pragma unroll
    for (int nn = 0; nn < 12; nn++)
        #pragma unroll
        for (int r = 0; r < 4; r++) o_acc[nn][r] = 0.f;

    int row_a0 = wid * 16 + g;
    int row_a1 = wid * 16 + g + 8;

    for (int jt = 0; jt < 16; jt++) {
        cp_wait<0>();
        __syncthreads();
        if (jt < 15) fill_kv((jt + 1) & 1, jt + 1);
        uint32_t* ksb = ks + (jt & 1) * 64 * KS_STRIDE;
        uint32_t* vsb = vs + (jt & 1) * 96 * VS_STRIDE;

        float sv[8][4];
        #pragma unroll
        for (int nn = 0; nn < 8; nn++)
            #pragma unroll
            for (int r = 0; r < 4; r++) sv[nn][r] = 0.f;

        #pragma unroll
        for (int kk = 0; kk < 12; kk++) {
            uint32_t a[4];
            uint2 qa0 = *(const uint2*)&qs[row_a0 * QS_STRIDE + kk * 8 + 2 * tig];
            uint2 qa1 = *(const uint2*)&qs[row_a1 * QS_STRIDE + kk * 8 + 2 * tig];
            a[0] = qa0.x; a[2] = qa0.y;
            a[1] = qa1.x; a[3] = qa1.y;
            #pragma unroll
            for (int nn = 0; nn < 8; nn++) {
                uint2 kb_ = *(const uint2*)&ksb[(nn * 8 + g) * KS_STRIDE + kk * 8 + 2 * tig];
                uint32_t bb[2] = {kb_.x, kb_.y};
                mma_tf32(sv[nn], a, bb);
            }
        }

        float rmax0 = -1e30f, rmax1 = -1e30f;
        #pragma unroll
        for (int nn = 0; nn < 8; nn++) {
            rmax0 = fmaxf(rmax0, fmaxf(sv[nn][0], sv[nn][1]));
            rmax1 = fmaxf(rmax1, fmaxf(sv[nn][2], sv[nn][3]));
        }
        #pragma unroll
        for (int o = 1; o <= 2; o <<= 1) {
            rmax0 = fmaxf(rmax0, __shfl_xor_sync(0xffffffffu, rmax0, o));
            rmax1 = fmaxf(rmax1, __shfl_xor_sync(0xffffffffu, rmax1, o));
        }
        float nm0 = fmaxf(m0, rmax0), nm1 = fmaxf(m1, rmax1);
        float corr0 = __expf(m0 - nm0), corr1 = __expf(m1 - nm1);
        float rs0 = 0.f, rs1 = 0.f;
        #pragma unroll
        for (int nn = 0; nn < 8; nn++) {
            float p00 = __expf(sv[nn][0] - nm0);
            float p01 = __expf(sv[nn][1] - nm0);
            float p10 = __expf(sv[nn][2] - nm1);
            float p11 = __expf(sv[nn][3] - nm1);
            rs0 += p00 + p01; rs1 += p10 + p11;
            int c = nn * 8 + tig * 2;
            pw[g * PS_STRIDE + KPERM(c)]           = f2tf32(p00);
            pw[g * PS_STRIDE + KPERM(c + 1)]       = f2tf32(p01);
            pw[(g + 8) * PS_STRIDE + KPERM(c)]     = f2tf32(p10);
            pw[(g + 8) * PS_STRIDE + KPERM(c + 1)] = f2tf32(p11);
        }
        #pragma unroll
        for (int o = 1; o <= 2; o <<= 1) {
            rs0 += __shfl_xor_sync(0xffffffffu, rs0, o);
            rs1 += __shfl_xor_sync(0xffffffffu, rs1, o);
        }
        l0 = l0 * corr0 + rs0;  m0 = nm0;
        l1 = l1 * corr1 + rs1;  m1 = nm1;
        #pragma unroll
        for (int nn = 0; nn < 12; nn++) {
            o_acc[nn][0] *= corr0; o_acc[nn][1] *= corr0;
            o_acc[nn][2] *= corr1; o_acc[nn][3] *= corr1;
        }
        __syncwarp();

        #pragma unroll
        for (int kk = 0; kk < 8; kk++) {
            uint32_t a[4];
            uint2 pa0 = *(const uint2*)&pw[g * PS_STRIDE + kk * 8 + 2 * tig];
            uint2 pa1 = *(const uint2*)&pw[(g + 8) * PS_STRIDE + kk * 8 + 2 * tig];
            a[0] = pa0.x; a[2] = pa0.y;
            a[1] = pa1.x; a[3] = pa1.y;
            #pragma unroll
            for (int nn = 0; nn < 12; nn++) {
                uint2 vb_ = *(const uint2*)&vsb[(nn * 8 + g) * VS_STRIDE + kk * 8 + 2 * tig];
                uint32_t bb[2] = {vb_.x, vb_.y};
                mma_tf32(o_acc[nn], a, bb);
            }
        }
        __syncwarp();
    }

    float inv0 = 1.f / l0, inv1 = 1.f / l1;
    int tok0 = b * N_ + i0 + row_a0;
    int tok1 = b * N_ + i0 + row_a1;
    int a0 = tok0 * H_ + h, a1 = tok1 * H_ + h;
    float ga0 = g_gate[a0], ga1 = g_gate[a1];
    #pragma unroll
    for (int nn = 0; nn < 12; nn++) {
        int c = nn * 8 + tig * 2;
        g_ot[(size_t)a0 * HD_ + KPERM(c)]     = f2tf32(ga0 * (o_acc[nn][0] * inv0));
        g_ot[(size_t)a0 * HD_ + KPERM(c + 1)] = f2tf32(ga0 * (o_acc[nn][1] * inv0));
        g_ot[(size_t)a1 * HD_ + KPERM(c)]     = f2tf32(ga1 * (o_acc[nn][2] * inv1));
        g_ot[(size_t)a1 * HD_ + KPERM(c + 1)] = f2tf32(ga1 * (o_acc[nn][3] * inv1));
    }
}

/* -- grouped reduce: 128-row tiles, cp.async dbuf, LDS.64, v2-red epilogue --- */
#define RED_SMEM_WORDS (128*100 + 2*48*100)   /* 89600 bytes */
__global__ void __launch_bounds__(256) red_tc_kernel(float* __restrict__ out) {
    int e = blockIdx.y;
    int count = g_ecount[e];
    int base = blockIdx.x * 128;
    if (base >= count) return;

    extern __shared__ uint32_t rsm[];
    uint32_t* osT = rsm;                      /* [128][100]   */
    uint32_t* w2T = rsm + 128 * 100;          /* [2][48][100] */
    __shared__ int s_a[128];

    int tid = threadIdx.x;
    if (tid < 128) {
        int idx = base + tid; if (idx >= count) idx = count - 1;
        s_a[tid] = g_elist[e * NA + idx];
    }
    __syncthreads();

    uint32_t osT_s = (uint32_t)__cvta_generic_to_shared(osT);
    uint32_t w2T_s = (uint32_t)__cvta_generic_to_shared(w2T);
    const uint32_t* w2te = g_w2t + (size_t)e * DIM_ * HD_;

    #pragma unroll
    for (int j = 0; j < 12; j++) {
        int item = tid + 256 * j;
        int r = item / 24, seg = item % 24;
        int a = s_a[r];
        cp_async16(osT_s + (r * 100 + seg * 4) * 4,
                   g_ot + (size_t)a * HD_ + seg * 4);
    }

    auto fill_w2 = [&](int bi, int ct) {
        uint32_t wb = w2T_s + bi * (48 * 100 * 4);
        const uint32_t* src = w2te + (size_t)(ct * 48) * HD_;
        #pragma unroll
        for (int j = 0; j < 5; j++) {
            int item = tid + 256 * j;
            if (item < 1152) {
                int c = item / 24, seg = item % 24;
                cp_async16(wb + (c * 100 + seg * 4) * 4,
                           src + (size_t)c * HD_ + seg * 4);
            }
        }
        cp_commit();
    };
    fill_w2(0, 0);

    int wid = tid >> 5, lane = tid & 31;
    int g = lane >> 2, tig = lane & 3;
    int row_a0 = wid * 16 + g, row_a1 = row_a0 + 8;
    bool ok0 = (base + row_a0 < count), ok1 = (base + row_a1 < count);
    int t0 = s_a[row_a0] >> 3, t1 = s_a[row_a1] >> 3;

    for (int ct = 0; ct < 16; ct++) {
        if (ct < 15) fill_w2((ct + 1) & 1, ct + 1);
        if (ct < 15) cp_wait<1>(); else cp_wait<0>();
        __syncthreads();
        uint32_t* wsb = w2T + (ct & 1) * 48 * 100;

        float acc[6][4];
        #pragma unroll
        for (int nn = 0; nn < 6; nn++)
            #pragma unroll
            for (int r = 0; r < 4; r++) acc[nn][r] = 0.f;

        #pragma unroll
        for (int kk = 0; kk < 12; kk++) {
            uint32_t a[4];
            uint2 oa0 = *(const uint2*)&osT[row_a0 * 100 + kk * 8 + 2 * tig];
            uint2 oa1 = *(const uint2*)&osT[row_a1 * 100 + kk * 8 + 2 * tig];
            a[0] = oa0.x; a[2] = oa0.y;
            a[1] = oa1.x; a[3] = oa1.y;
            #pragma unroll
            for (int nn = 0; nn < 6; nn++) {
                uint2 wb_ = *(const uint2*)&wsb[(nn * 8 + g) * 100 + kk * 8 + 2 * tig];
                uint32_t bb[2] = {wb_.x, wb_.y};
                mma_tf32(acc[nn], a, bb);
            }
        }

        #pragma unroll
        for (int nn = 0; nn < 6; nn++) {
            int c = ct * 48 + nn * 8 + tig * 2;
            if (ok0) red_add_v2(&out[(size_t)t0 * DIM_ + c], acc[nn][0], acc[nn][1]);
            if (ok1) red_add_v2(&out[(size_t)t1 * DIM_ + c], acc[nn][2], acc[nn][3]);
        }
        __syncthreads();
    }
}

/* ------------- aux loss + restore zeroed gating state for next run ---------- */
__global__ void aux_kernel(float* __restrict__ out, int out_size) {
    int tid = threadIdx.x;
    if (tid == 0) {
        float mesum = 0.f;
        for (int e = 0; e < E_; e++) mesum += g_me[e];
        float sw = 0.f;
        for (int e = 0; e < E_; e++)
            sw += (g_me[e] / mesum) * ((float)g_ecount[e] / (float)NA);
        sw *= (float)E_;
        float z = g_z / (float)NT;
        float aux = 0.1f * sw + 0.001f * z;
        if (out_size > NT * DIM_) out[out_size - 1] = aux;
    }
    __syncwarp();
    if (tid < E_) { g_me[tid] = 0.f; g_ecount[tid] = 0; }
    if (tid == 0) g_z = 0.f;
}

/* -------------------------------- launch ------------------------------------ */
extern "C" void kernel_launch(void* const* d_in, const int* in_sizes, int n_in,
                              void* d_out, int out_size) {
    const float* x    = (const float*)d_in[0];
    const float* Wg   = (const float*)d_in[1];
    const float* W1   = (const float*)d_in[2];
    const float* W2   = (const float*)d_in[3];
    const float* Wkv  = (const float*)d_in[4];
    const float* bkv  = (const float*)d_in[5];
    const int*   task = (const int*)d_in[6];
    float* out = (float*)d_out;

    cudaFuncSetAttribute(attn_tc_kernel,
                         cudaFuncAttributeMaxDynamicSharedMemorySize,
                         ATTN_SMEM_WORDS * (int)sizeof(uint32_t));
    cudaFuncSetAttribute(red_tc_kernel,
                         cudaFuncAttributeMaxDynamicSharedMemorySize,
                         RED_SMEM_WORDS * (int)sizeof(uint32_t));
    cudaFuncSetAttribute(q_tc_kernel,
                         cudaFuncAttributeMaxDynamicSharedMemorySize,
                         Q_SMEM_WORDS * (int)sizeof(uint32_t));

    prep_kernel<<<1536, 256>>>(x, Wg, W1, W2, Wkv, bkv, task, out, out_size); /* #1 */
    q_tc_kernel<<<dim3(64, E_), 256, Q_SMEM_WORDS * sizeof(uint32_t)>>>();   /* #2 */
    attn_tc_kernel<<<dim3(8, B_ * H_), 256,
                     ATTN_SMEM_WORDS * sizeof(uint32_t)>>>();                /* #3 */
    red_tc_kernel<<<dim3(64, E_), 256,
                    RED_SMEM_WORDS * sizeof(uint32_t)>>>(out);               /* #4 */
    aux_kernel<<<1, 32>>>(out, out_size);                                    /* #5 */
}

// round 15
// speedup vs baseline: 1.2962x; 1.2962x over previous
#include <cuda_runtime.h>
#include <math.h>
#include <stdint.h>

#define B_    8
#define N_    1024
#define DIM_  768
#define H_    8
#define HD_   96
#define E_    24
#define NT    (B_*N_)      /* 8192 tokens */
#define NA    (NT*H_)      /* 65536 assignments */
#define SCALE_ 0.10206207261596575f  /* 96^-0.5 */

/* k-group permutation: word for logical index d lives at KPERM(d).
   Within each 8-word group, fragment pairs (i, i+4) land adjacent (2i, 2i+1). */
#define KPERM(d) (((d) & ~7) | (((d) & 3) << 1) | (((d) >> 2) & 1))

/* ------------------------- scratch (device globals) ------------------------- */
__device__ float    g_gate[NA];
__device__ float    g_me[E_];        /* zero-init; aux re-zeroes each run */
__device__ float    g_z;
__device__ int      g_ecount[E_];
__device__ int      g_elist[E_*NA];
__device__ uint32_t g_kt[NT*HD_];                 /* k tf32, k-permuted          */
__device__ uint32_t g_vtT[NT*HD_];                /* v tf32 transposed [b][d][j] */
__device__ uint32_t g_qt[(size_t)NA*HD_];         /* q*scale tf32, k-permuted    */
__device__ uint32_t g_ot[(size_t)NA*HD_];         /* gate*o tf32, k-permuted     */
__device__ uint32_t g_xt[(size_t)NT*DIM_];        /* x tf32, k-permuted          */
__device__ uint32_t g_w1t[(size_t)E_*HD_*DIM_];   /* W1^T [e][c][k], permuted    */
__device__ uint32_t g_w2t[(size_t)E_*DIM_*HD_];   /* W2^T [e][c][k], permuted    */

__device__ __forceinline__ uint32_t f2tf32(float f) {
    uint32_t r;
    asm("cvt.rna.tf32.f32 %0, %1;" : "=r"(r) : "f"(f));
    return r;
}

__device__ __forceinline__ void mma_tf32(float* d, const uint32_t* a, const uint32_t* b) {
    asm("mma.sync.aligned.m16n8k8.row.col.f32.tf32.tf32.f32 "
        "{%0,%1,%2,%3}, {%4,%5,%6,%7}, {%8,%9}, {%0,%1,%2,%3};"
        : "+f"(d[0]), "+f"(d[1]), "+f"(d[2]), "+f"(d[3])
        : "r"(a[0]), "r"(a[1]), "r"(a[2]), "r"(a[3]), "r"(b[0]), "r"(b[1]));
}

__device__ __forceinline__ void red_add_v2(float* addr, float a, float b) {
    asm volatile("red.global.add.v2.f32 [%0], {%1, %2};"
                 :: "l"(addr), "f"(a), "f"(b) : "memory");
}

__device__ __forceinline__ void cp_async16(uint32_t dst_smem, const void* src) {
    asm volatile("cp.async.cg.shared.global [%0], [%1], 16;"
                 :: "r"(dst_smem), "l"(src));
}
__device__ __forceinline__ void cp_commit() {
    asm volatile("cp.async.commit_group;");
}
template<int N> __device__ __forceinline__ void cp_wait() {
    asm volatile("cp.async.wait_group %0;" :: "n"(N));
}

/* ===== prep: gate+preconvert (0-1023) | kv (1024-1279) | zero (1280-1535) ===== */
__global__ void prep_kernel(const float* __restrict__ x,
                            const float* __restrict__ Wg,
                            const float* __restrict__ W1,
                            const float* __restrict__ W2,
                            const float* __restrict__ Wkv,
                            const float* __restrict__ bkv,
                            const int*   __restrict__ task_p,
                            float* __restrict__ out, int out_size) {
    __shared__ float sbuf[4352];
    __shared__ float sme[E_];
    __shared__ float szv;
    __shared__ int   scnt[E_];
    __shared__ int   sbase[E_];
    int bx  = blockIdx.x;
    int tid = threadIdx.x;

    if (bx < 1024) {
        /* ------------------- gating ------------------- */
        int warp = tid >> 5, lane = tid & 31;
        int t = bx * 8 + warp;
        if (tid < E_) { sme[tid] = 0.f; scnt[tid] = 0; }
        if (tid == 0) szv = 0.f;
        __syncthreads();

        int task = *task_p;
        const float* wg = Wg + (size_t)task * DIM_ * E_;
        const float* xr = x + (size_t)t * DIM_;

        float acc = 0.f;
        if (lane < E_) {
            #pragma unroll 4
            for (int d = 0; d < DIM_; d++) acc += xr[d] * wg[d * E_ + lane];
        }
        float logit = (lane < E_) ? acc : -1e30f;

        float m = logit;
        #pragma unroll
        for (int o = 16; o >= 1; o >>= 1) m = fmaxf(m, __shfl_xor_sync(0xffffffffu, m, o));
        float p = (lane < E_) ? expf(logit - m) : 0.f;
        float s = p;
        #pragma unroll
        for (int o = 16; o >= 1; o >>= 1) s += __shfl_xor_sync(0xffffffffu, s, o);
        float prob = p / s;
        float lse = m + logf(s);
        if (lane == 0) atomicAdd(&szv, lse * lse);
        if (lane < E_) atomicAdd(&sme[lane], prob);

        float val = (lane < E_) ? prob : -1.f;
        float sel_g = 0.f; int sel_e = 0;
        #pragma unroll
        for (int it = 0; it < H_; it++) {
            float mm = val;
            #pragma unroll
            for (int o = 16; o >= 1; o >>= 1)
                mm = fmaxf(mm, __shfl_xor_sync(0xffffffffu, mm, o));
            unsigned msk = __ballot_sync(0xffffffffu, val == mm);
            int src = __ffs(msk) - 1;
            if (lane == src) val = -1.f;
            if (lane == it) { sel_e = src; sel_g = mm; }
        }
        float gv = (lane < H_) ? sel_g : 0.f;
        #pragma unroll
        for (int o = 16; o >= 1; o >>= 1) gv += __shfl_xor_sync(0xffffffffu, gv, o);
        float denom = gv + 1e-6f;

        int pos = 0;
        if (lane < H_) pos = atomicAdd(&scnt[sel_e], 1);
        __syncthreads();
        if (tid < E_) sbase[tid] = atomicAdd(&g_ecount[tid], scnt[tid]);
        __syncthreads();
        if (lane < H_) {
            int a = t * H_ + lane;
            g_gate[a] = sel_g / denom;
            g_elist[sel_e * NA + sbase[sel_e] + pos] = a;
        }
        if (tid < E_) atomicAdd(&g_me[tid], sme[tid]);
        if (tid == 0) atomicAdd(&g_z, szv);

        /* ---- pre-convert x -> g_xt (tf32, k-permuted per 8-group) ---- */
        {
            const float4* xin = (const float4*)x;
            uint4* xout = (uint4*)g_xt;
            int gbase = bx * 768;              /* 8-word groups per block */
            for (int i = tid; i < 768; i += 256) {
                int gi = gbase + i;
                float4 in0 = xin[2 * gi], in1 = xin[2 * gi + 1];
                uint4 lo, hi;
                lo.x = f2tf32(in0.x); lo.y = f2tf32(in1.x);
                lo.z = f2tf32(in0.y); lo.w = f2tf32(in1.y);
                hi.x = f2tf32(in0.z); hi.y = f2tf32(in1.z);
                hi.z = f2tf32(in0.w); hi.w = f2tf32(in1.w);
                xout[2 * gi]     = lo;
                xout[2 * gi + 1] = hi;
            }
        }

        /* ---- W1 -> g_w1t [e][c][k] permuted (1728 tiles) ---- */
        float (*tile)[33] = (float(*)[33])sbuf;
        int ty = tid >> 5, tx8 = tid & 31;
        int kp = KPERM(tx8);
        for (int tix = bx; tix < 1728; tix += 1024) {
            int e  = tix / 72;
            int rem = tix % 72;
            int kt = rem / 3, ct = rem % 3;
            __syncthreads();
            for (int r = ty; r < 32; r += 8)
                tile[r][tx8] = W1[((size_t)e * DIM_ + kt * 32 + r) * HD_ + ct * 32 + tx8];
            __syncthreads();
            for (int r = ty; r < 32; r += 8)
                g_w1t[((size_t)e * HD_ + ct * 32 + r) * DIM_ + kt * 32 + kp] =
                    f2tf32(tile[tx8][r]);
        }

        /* ---- W2 -> g_w2t [e][c][k] permuted (1728 tiles; W2 is [e][96][768]) ---- */
        for (int tix = bx; tix < 1728; tix += 1024) {
            int e  = tix / 72;
            int rem = tix % 72;
            int kt = rem / 24, ct = rem % 24;
            __syncthreads();
            for (int r = ty; r < 32; r += 8)
                tile[r][tx8] = W2[((size_t)e * HD_ + kt * 32 + r) * DIM_ + ct * 32 + tx8];
            __syncthreads();
            for (int r = ty; r < 32; r += 8)
                g_w2t[((size_t)e * DIM_ + ct * 32 + r) * HD_ + kt * 32 + kp] =
                    f2tf32(tile[tx8][r]);
        }
    } else if (bx < 1280) {
        /* ---- kv projection: 64 rows x 96 cols per block; two 48-col passes ----
           outputs: k -> g_kt (k-permuted), v -> g_vtT [b][d][j] (j-permuted)   */
        float (*xsT)[68] = (float(*)[68])sbuf;            /* [32][68] = 2176 */
        float (*ws)[52]  = (float(*)[52])(sbuf + 32 * 68); /* [32][52] = 1664 */
        int i = bx - 1024;                 /* 0..255 */
        int r0 = (i & 127) * 64;           /* 128 row-tiles */
        int c0 = (i >> 7) * 96;            /* 0 = k cols, 96 = v cols */
        int ty = tid >> 4, tx = tid & 15;  /* 16x16 threads: 4 rows x 3 cols each */

        for (int half = 0; half < 2; half++) {
            int ch0 = c0 + half * 48;
            float acc[4][3] = {};
            for (int k0 = 0; k0 < DIM_; k0 += 32) {
                __syncthreads();
                for (int ii = tid; ii < 64 * 32; ii += 256) {
                    int r = ii >> 5, k = ii & 31;
                    xsT[k][r] = x[(size_t)(r0 + r) * DIM_ + k0 + k];
                }
                for (int ii = tid; ii < 32 * 48; ii += 256) {
                    int k = ii / 48, c = ii % 48;
                    ws[k][c] = Wkv[(size_t)(k0 + k) * (2 * HD_) + ch0 + c];
                }
                __syncthreads();
                #pragma unroll
                for (int k = 0; k < 32; k++) {
                    float4 a4 = *(const float4*)&xsT[k][ty * 4];
                    float av[4] = {a4.x, a4.y, a4.z, a4.w};
                    float bv[3];
                    #pragma unroll
                    for (int j = 0; j < 3; j++) bv[j] = ws[k][tx + 16 * j];
                    #pragma unroll
                    for (int ri = 0; ri < 4; ri++)
                        #pragma unroll
                        for (int cj = 0; cj < 3; cj++)
                            acc[ri][cj] += av[ri] * bv[cj];
                }
            }
            #pragma unroll
            for (int ri = 0; ri < 4; ri++) {
                int r = r0 + ty * 4 + ri;
                #pragma unroll
                for (int cj = 0; cj < 3; cj++) {
                    int c = ch0 + tx + 16 * cj;
                    uint32_t v = f2tf32(acc[ri][cj] + bkv[c]);
                    if (c < HD_) {
                        g_kt[(size_t)r * HD_ + KPERM(c)] = v;
                    } else {
                        int d = c - HD_;
                        int bb = r >> 10, n = r & (N_ - 1);
                        g_vtT[((size_t)bb * HD_ + d) * N_ + KPERM(n)] = v;
                    }
                }
            }
        }
    } else {
        /* ------------------- zero output ------------------- */
        int zb = bx - 1280;                /* 0..255 */
        float4* o4 = (float4*)out;
        const int n4 = NT * DIM_ / 4;
        for (int i = zb * 256 + tid; i < n4; i += 256 * 256)
            o4[i] = make_float4(0.f, 0.f, 0.f, 0.f);
        for (int i = NT * DIM_ + zb * 256 + tid; i < out_size; i += 256 * 256)
            out[i] = 0.f;
    }
}

/* ------- grouped q projection: cp.async dbuf, conflict-free LDS.64 ---------- */
/* strides 40 (== 8 mod 32): 8-byte fragment loads hit distinct banks          */
#define QX_STR 40
#define Q_SMEM_WORDS (2*128*QX_STR + 2*96*QX_STR)
__global__ void __launch_bounds__(256) q_tc_kernel() {
    int e = blockIdx.y;
    int count = g_ecount[e];
    int base = blockIdx.x * 128;
    if (base >= count) return;

    extern __shared__ uint32_t qsm[];
    uint32_t* xs = qsm;
    uint32_t* ws = qsm + 2 * 128 * QX_STR;
    __shared__ int s_a[128];
    int tid = threadIdx.x;
    if (tid < 128) {
        int idx = base + tid; if (idx >= count) idx = count - 1;
        s_a[tid] = g_elist[e * NA + idx];
    }
    __syncthreads();

    uint32_t xs_smem = (uint32_t)__cvta_generic_to_shared(xs);
    uint32_t ws_smem = (uint32_t)__cvta_generic_to_shared(ws);
    const uint32_t* w1t = g_w1t + (size_t)e * HD_ * DIM_;

    int wid = tid >> 5, lane = tid & 31;
    int g = lane >> 2, tig = lane & 3;
    int row_a0 = wid * 16 + g, row_a1 = row_a0 + 8;

    float acc[12][4];
    #pragma unroll
    for (int nn = 0; nn < 12; nn++)
        #pragma unroll
        for (int r = 0; r < 4; r++) acc[nn][r] = 0.f;

    auto fill = [&](int bi, int k0) {
        uint32_t xb = xs_smem + bi * (128 * QX_STR * 4);
        uint32_t wb = ws_smem + bi * (96 * QX_STR * 4);
        #pragma unroll
        for (int j = 0; j < 4; j++) {
            int item = tid + 256 * j;
            int r = item >> 3, seg = item & 7;
            int tok = s_a[r] >> 3;
            cp_async16(xb + (r * QX_STR + seg * 4) * 4,
                       g_xt + (size_t)tok * DIM_ + k0 + seg * 4);
        }
        #pragma unroll
        for (int j = 0; j < 3; j++) {
            int item = tid + 256 * j;
            int c = item >> 3, seg = item & 7;
            cp_async16(wb + (c * QX_STR + seg * 4) * 4,
                       w1t + (size_t)c * DIM_ + k0 + seg * 4);
        }
        cp_commit();
    };

    fill(0, 0);
    for (int c = 0; c < 24; c++) {
        if (c < 23) fill((c + 1) & 1, (c + 1) * 32);
        if (c < 23) cp_wait<1>(); else cp_wait<0>();
        __syncthreads();
        uint32_t* xsb = xs + (c & 1) * 128 * QX_STR;
        uint32_t* wsb = ws + (c & 1) * 96 * QX_STR;
        #pragma unroll
        for (int kk = 0; kk < 4; kk++) {
            uint32_t a[4];
            uint2 xa0 = *(const uint2*)&xsb[row_a0 * QX_STR + kk * 8 + 2 * tig];
            uint2 xa1 = *(const uint2*)&xsb[row_a1 * QX_STR + kk * 8 + 2 * tig];
            a[0] = xa0.x; a[2] = xa0.y;
            a[1] = xa1.x; a[3] = xa1.y;
            #pragma unroll
            for (int nn = 0; nn < 12; nn++) {
                uint2 wb_ = *(const uint2*)&wsb[(nn * 8 + g) * QX_STR + kk * 8 + 2 * tig];
                uint32_t bb[2] = {wb_.x, wb_.y};
                mma_tf32(acc[nn], a, bb);
            }
        }
        __syncthreads();
    }

    bool ok0 = (base + row_a0 < count), ok1 = (base + row_a1 < count);
    int a0 = s_a[row_a0], a1 = s_a[row_a1];
    #pragma unroll
    for (int nn = 0; nn < 12; nn++) {
        int c = nn * 8 + tig * 2;
        if (ok0) {
            g_qt[(size_t)a0 * HD_ + KPERM(c)]     = f2tf32(acc[nn][0] * SCALE_);
            g_qt[(size_t)a0 * HD_ + KPERM(c + 1)] = f2tf32(acc[nn][1] * SCALE_);
        }
        if (ok1) {
            g_qt[(size_t)a1 * HD_ + KPERM(c)]     = f2tf32(acc[nn][2] * SCALE_);
            g_qt[(size_t)a1 * HD_ + KPERM(c + 1)] = f2tf32(acc[nn][3] * SCALE_);
        }
    }
}

/* ------- fused flash attention: cp.async dbuf, conflict-free LDS.64 --------- */
#define QS_STRIDE 104
#define KS_STRIDE 104
#define VS_STRIDE 72
#define PS_STRIDE 72
#define ATTN_SMEM_WORDS (128*QS_STRIDE + 2*64*KS_STRIDE + 2*96*VS_STRIDE + 8*16*PS_STRIDE)

__global__ void __launch_bounds__(256, 1) attn_tc_kernel() {
    extern __shared__ uint32_t smu[];
    uint32_t* qs = smu;                                    /* [128][104]   */
    uint32_t* ks = qs + 128 * QS_STRIDE;                   /* [2][64][104] */
    uint32_t* vs = ks + 2 * 64 * KS_STRIDE;                /* [2][96][72]  */
    uint32_t* ps = vs + 2 * 96 * VS_STRIDE;                /* [8][16][72]  */

    int it = blockIdx.x, bh = blockIdx.y;
    int b = bh >> 3, h = bh & 7;
    int i0 = it * 128;
    int tid  = threadIdx.x;
    int wid  = tid >> 5;
    int lane = tid & 31;
    int g    = lane >> 2;
    int tig  = lane & 3;
    uint32_t* pw = ps + wid * 16 * PS_STRIDE;

    uint32_t qs_s = (uint32_t)__cvta_generic_to_shared(qs);
    uint32_t ks_s = (uint32_t)__cvta_generic_to_shared(ks);
    uint32_t vs_s = (uint32_t)__cvta_generic_to_shared(vs);

    #pragma unroll
    for (int j = 0; j < 12; j++) {
        int item = tid + 256 * j;
        int r = item / 24, seg = item % 24;
        cp_async16(qs_s + (r * QS_STRIDE + seg * 4) * 4,
                   g_qt + ((size_t)(b * N_ + i0 + r) * H_ + h) * HD_ + seg * 4);
    }
    cp_commit();

    auto fill_kv = [&](int bi, int jt) {
        int j0 = jt * 64;
        uint32_t kb = ks_s + bi * (64 * KS_STRIDE * 4);
        uint32_t vb = vs_s + bi * (96 * VS_STRIDE * 4);
        #pragma unroll
        for (int j = 0; j < 6; j++) {          /* K: 64 rows x 24 segs */
            int item = tid + 256 * j;
            int r = item / 24, seg = item % 24;
            cp_async16(kb + (r * KS_STRIDE + seg * 4) * 4,
                       g_kt + (size_t)(b * N_ + j0 + r) * HD_ + seg * 4);
        }
        #pragma unroll
        for (int j = 0; j < 6; j++) {          /* V^T: 96 rows x 16 segs */
            int item = tid + 256 * j;
            int d = item >> 4, seg = item & 15;
            cp_async16(vb + (d * VS_STRIDE + seg * 4) * 4,
                       g_vtT + ((size_t)b * HD_ + d) * N_ + j0 + seg * 4);
        }
        cp_commit();
    };
    fill_kv(0, 0);

    float m0 = -1e30f, m1 = -1e30f, l0 = 0.f, l1 = 0.f;
    float o_acc[12][4];
    #pragma unroll
    for (int nn = 0; nn < 12; nn++)
        #pragma unroll
        for (int r = 0; r < 4; r++) o_acc[nn][r] = 0.f;

    int row_a0 = wid * 16 + g;
    int row_a1 = wid * 16 + g + 8;

    for (int jt = 0; jt < 16; jt++) {
        cp_wait<0>();
        __syncthreads();
        if (jt < 15) fill_kv((jt + 1) & 1, jt + 1);
        uint32_t* ksb = ks + (jt & 1) * 64 * KS_STRIDE;
        uint32_t* vsb = vs + (jt & 1) * 96 * VS_STRIDE;

        float sv[8][4];
        #pragma unroll
        for (int nn = 0; nn < 8; nn++)
            #pragma unroll
            for (int r = 0; r < 4; r++) sv[nn][r] = 0.f;

        #pragma unroll
        for (int kk = 0; kk < 12; kk++) {
            uint32_t a[4];
            uint2 qa0 = *(const uint2*)&qs[row_a0 * QS_STRIDE + kk * 8 + 2 * tig];
            uint2 qa1 = *(const uint2*)&qs[row_a1 * QS_STRIDE + kk * 8 + 2 * tig];
            a[0] = qa0.x; a[2] = qa0.y;
            a[1] = qa1.x; a[3] = qa1.y;
            #pragma unroll
            for (int nn = 0; nn < 8; nn++) {
                uint2 kb_ = *(const uint2*)&ksb[(nn * 8 + g) * KS_STRIDE + kk * 8 + 2 * tig];
                uint32_t bb[2] = {kb_.x, kb_.y};
                mma_tf32(sv[nn], a, bb);
            }
        }

        float rmax0 = -1e30f, rmax1 = -1e30f;
        #pragma unroll
        for (int nn = 0; nn < 8; nn++) {
            rmax0 = fmaxf(rmax0, fmaxf(sv[nn][0], sv[nn][1]));
            rmax1 = fmaxf(rmax1, fmaxf(sv[nn][2], sv[nn][3]));
        }
        #pragma unroll
        for (int o = 1; o <= 2; o <<= 1) {
            rmax0 = fmaxf(rmax0, __shfl_xor_sync(0xffffffffu, rmax0, o));
            rmax1 = fmaxf(rmax1, __shfl_xor_sync(0xffffffffu, rmax1, o));
        }
        float nm0 = fmaxf(m0, rmax0), nm1 = fmaxf(m1, rmax1);
        float corr0 = __expf(m0 - nm0), corr1 = __expf(m1 - nm1);
        float rs0 = 0.f, rs1 = 0.f;
        #pragma unroll
        for (int nn = 0; nn < 8; nn++) {
            float p00 = __expf(sv[nn][0] - nm0);
            float p01 = __expf(sv[nn][1] - nm0);
            float p10 = __expf(sv[nn][2] - nm1);
            float p11 = __expf(sv[nn][3] - nm1);
            rs0 += p00 + p01; rs1 += p10 + p11;
            int c = nn * 8 + tig * 2;
            pw[g * PS_STRIDE + KPERM(c)]           = f2tf32(p00);
            pw[g * PS_STRIDE + KPERM(c + 1)]       = f2tf32(p01);
            pw[(g + 8) * PS_STRIDE + KPERM(c)]     = f2tf32(p10);
            pw[(g + 8) * PS_STRIDE + KPERM(c + 1)] = f2tf32(p11);
        }
        #pragma unroll
        for (int o = 1; o <= 2; o <<= 1) {
            rs0 += __shfl_xor_sync(0xffffffffu, rs0, o);
            rs1 += __shfl_xor_sync(0xffffffffu, rs1, o);
        }
        l0 = l0 * corr0 + rs0;  m0 = nm0;
        l1 = l1 * corr1 + rs1;  m1 = nm1;
        #pragma unroll
        for (int nn = 0; nn < 12; nn++) {
            o_acc[nn][0] *= corr0; o_acc[nn][1] *= corr0;
            o_acc[nn][2] *= corr1; o_acc[nn][3] *= corr1;
        }
        __syncwarp();

        #pragma unroll
        for (int kk = 0; kk < 8; kk++) {
            uint32_t a[4];
            uint2 pa0 = *(const uint2*)&pw[g * PS_STRIDE + kk * 8 + 2 * tig];
            uint2 pa1 = *(const uint2*)&pw[(g + 8) * PS_STRIDE + kk * 8 + 2 * tig];
            a[0] = pa0.x; a[2] = pa0.y;
            a[1] = pa1.x; a[3] = pa1.y;
            #pragma unroll
            for (int nn = 0; nn < 12; nn++) {
                uint2 vb_ = *(const uint2*)&vsb[(nn * 8 + g) * VS_STRIDE + kk * 8 + 2 * tig];
                uint32_t bb[2] = {vb_.x, vb_.y};
                mma_tf32(o_acc[nn], a, bb);
            }
        }
        __syncwarp();
    }

    float inv0 = 1.f / l0, inv1 = 1.f / l1;
    int tok0 = b * N_ + i0 + row_a0;
    int tok1 = b * N_ + i0 + row_a1;
    int a0 = tok0 * H_ + h, a1 = tok1 * H_ + h;
    float ga0 = g_gate[a0], ga1 = g_gate[a1];
    #pragma unroll
    for (int nn = 0; nn < 12; nn++) {
        int c = nn * 8 + tig * 2;
        g_ot[(size_t)a0 * HD_ + KPERM(c)]     = f2tf32(ga0 * (o_acc[nn][0] * inv0));
        g_ot[(size_t)a0 * HD_ + KPERM(c + 1)] = f2tf32(ga0 * (o_acc[nn][1] * inv0));
        g_ot[(size_t)a1 * HD_ + KPERM(c)]     = f2tf32(ga1 * (o_acc[nn][2] * inv1));
        g_ot[(size_t)a1 * HD_ + KPERM(c + 1)] = f2tf32(ga1 * (o_acc[nn][3] * inv1));
    }
}

/* -- grouped reduce: 128-row tiles, cp.async dbuf, conflict-free LDS.64 ------ */
#define RD_STR 104
#define RED_SMEM_WORDS (128*RD_STR + 2*48*RD_STR)   /* 93184 bytes */
__global__ void __launch_bounds__(256) red_tc_kernel(float* __restrict__ out) {
    int e = blockIdx.y;
    int count = g_ecount[e];
    int base = blockIdx.x * 128;
    if (base >= count) return;

    extern __shared__ uint32_t rsm[];
    uint32_t* osT = rsm;                      /* [128][104]   */
    uint32_t* w2T = rsm + 128 * RD_STR;       /* [2][48][104] */
    __shared__ int s_a[128];

    int tid = threadIdx.x;
    if (tid < 128) {
        int idx = base + tid; if (idx >= count) idx = count - 1;
        s_a[tid] = g_elist[e * NA + idx];
    }
    __syncthreads();

    uint32_t osT_s = (uint32_t)__cvta_generic_to_shared(osT);
    uint32_t w2T_s = (uint32_t)__cvta_generic_to_shared(w2T);
    const uint32_t* w2te = g_w2t + (size_t)e * DIM_ * HD_;

    #pragma unroll
    for (int j = 0; j < 12; j++) {
        int item = tid + 256 * j;
        int r = item / 24, seg = item % 24;
        int a = s_a[r];
        cp_async16(osT_s + (r * RD_STR + seg * 4) * 4,
                   g_ot + (size_t)a * HD_ + seg * 4);
    }

    auto fill_w2 = [&](int bi, int ct) {
        uint32_t wb = w2T_s + bi * (48 * RD_STR * 4);
        const uint32_t* src = w2te + (size_t)(ct * 48) * HD_;
        #pragma unroll
        for (int j = 0; j < 5; j++) {
            int item = tid + 256 * j;
            if (item < 1152) {
                int c = item / 24, seg = item % 24;
                cp_async16(wb + (c * RD_STR + seg * 4) * 4,
                           src + (size_t)c * HD_ + seg * 4);
            }
        }
        cp_commit();
    };
    fill_w2(0, 0);

    int wid = tid >> 5, lane = tid & 31;
    int g = lane >> 2, tig = lane & 3;
    int row_a0 = wid * 16 + g, row_a1 = row_a0 + 8;
    bool ok0 = (base + row_a0 < count), ok1 = (base + row_a1 < count);
    int t0 = s_a[row_a0] >> 3, t1 = s_a[row_a1] >> 3;

    for (int ct = 0; ct < 16; ct++) {
        if (ct < 15) fill_w2((ct + 1) & 1, ct + 1);
        if (ct < 15) cp_wait<1>(); else cp_wait<0>();
        __syncthreads();
        uint32_t* wsb = w2T + (ct & 1) * 48 * RD_STR;

        float acc[6][4];
        #pragma unroll
        for (int nn = 0; nn < 6; nn++)
            #pragma unroll
            for (int r = 0; r < 4; r++) acc[nn][r] = 0.f;

        #pragma unroll
        for (int kk = 0; kk < 12; kk++) {
            uint32_t a[4];
            uint2 oa0 = *(const uint2*)&osT[row_a0 * RD_STR + kk * 8 + 2 * tig];
            uint2 oa1 = *(const uint2*)&osT[row_a1 * RD_STR + kk * 8 + 2 * tig];
            a[0] = oa0.x; a[2] = oa0.y;
            a[1] = oa1.x; a[3] = oa1.y;
            #pragma unroll
            for (int nn = 0; nn < 6; nn++) {
                uint2 wb_ = *(const uint2*)&wsb[(nn * 8 + g) * RD_STR + kk * 8 + 2 * tig];
                uint32_t bb[2] = {wb_.x, wb_.y};
                mma_tf32(acc[nn], a, bb);
            }
        }

        #pragma unroll
        for (int nn = 0; nn < 6; nn++) {
            int c = ct * 48 + nn * 8 + tig * 2;
            if (ok0) red_add_v2(&out[(size_t)t0 * DIM_ + c], acc[nn][0], acc[nn][1]);
            if (ok1) red_add_v2(&out[(size_t)t1 * DIM_ + c], acc[nn][2], acc[nn][3]);
        }
        __syncthreads();
    }
}

/* ------------- aux loss + restore zeroed gating state for next run ---------- */
__global__ void aux_kernel(float* __restrict__ out, int out_size) {
    int tid = threadIdx.x;
    if (tid == 0) {
        float mesum = 0.f;
        for (int e = 0; e < E_; e++) mesum += g_me[e];
        float sw = 0.f;
        for (int e = 0; e < E_; e++)
            sw += (g_me[e] / mesum) * ((float)g_ecount[e] / (float)NA);
        sw *= (float)E_;
        float z = g_z / (float)NT;
        float aux = 0.1f * sw + 0.001f * z;
        if (out_size > NT * DIM_) out[out_size - 1] = aux;
    }
    __syncwarp();
    if (tid < E_) { g_me[tid] = 0.f; g_ecount[tid] = 0; }
    if (tid == 0) g_z = 0.f;
}

/* -------------------------------- launch ------------------------------------ */
extern "C" void kernel_launch(void* const* d_in, const int* in_sizes, int n_in,
                              void* d_out, int out_size) {
    const float* x    = (const float*)d_in[0];
    const float* Wg   = (const float*)d_in[1];
    const float* W1   = (const float*)d_in[2];
    const float* W2   = (const float*)d_in[3];
    const float* Wkv  = (const float*)d_in[4];
    const float* bkv  = (const float*)d_in[5];
    const int*   task = (const int*)d_in[6];
    float* out = (float*)d_out;

    cudaFuncSetAttribute(attn_tc_kernel,
                         cudaFuncAttributeMaxDynamicSharedMemorySize,
                         ATTN_SMEM_WORDS * (int)sizeof(uint32_t));
    cudaFuncSetAttribute(red_tc_kernel,
                         cudaFuncAttributeMaxDynamicSharedMemorySize,
                         RED_SMEM_WORDS * (int)sizeof(uint32_t));
    cudaFuncSetAttribute(q_tc_kernel,
                         cudaFuncAttributeMaxDynamicSharedMemorySize,
                         Q_SMEM_WORDS * (int)sizeof(uint32_t));

    prep_kernel<<<1536, 256>>>(x, Wg, W1, W2, Wkv, bkv, task, out, out_size); /* #1 */
    q_tc_kernel<<<dim3(64, E_), 256, Q_SMEM_WORDS * sizeof(uint32_t)>>>();   /* #2 */
    attn_tc_kernel<<<dim3(8, B_ * H_), 256,
                     ATTN_SMEM_WORDS * sizeof(uint32_t)>>>();                /* #3 */
    red_tc_kernel<<<dim3(64, E_), 256,
                    RED_SMEM_WORDS * sizeof(uint32_t)>>>(out);               /* #4 */
    aux_kernel<<<1, 32>>>(out, out_size);                                    /* #5 */
}

// round 16
// speedup vs baseline: 1.3765x; 1.0619x over previous
#include <cuda_runtime.h>
#include <math.h>
#include <stdint.h>

#define B_    8
#define N_    1024
#define DIM_  768
#define H_    8
#define HD_   96
#define E_    24
#define NT    (B_*N_)      /* 8192 tokens */
#define NA    (NT*H_)      /* 65536 assignments */
#define SCALE_ 0.10206207261596575f  /* 96^-0.5 */

/* k-group permutation (reduce inputs only): pairs (i,i+4) -> adjacent (2i,2i+1) */
#define KPERM(d) (((d) & ~7) | (((d) & 3) << 1) | (((d) >> 2) & 1))

/* ------------------------- scratch (device globals) ------------------------- */
__device__ float    g_gate[NA];
__device__ float    g_me[E_];        /* zero-init; aux re-zeroes each run */
__device__ float    g_z;
__device__ int      g_ecount[E_];
__device__ int      g_elist[E_*NA];
__device__ uint32_t g_kt[NT*HD_];                 /* k tf32 (plain layout)       */
__device__ uint32_t g_vt[NT*HD_];                 /* v tf32 (plain layout)       */
__device__ uint32_t g_qt[(size_t)NA*HD_];         /* q*scale tf32 (plain)        */
__device__ uint32_t g_ot[(size_t)NA*HD_];         /* gate*o tf32, KPERM'd        */
__device__ uint32_t g_xt[(size_t)NT*DIM_];        /* x tf32 (plain)              */
__device__ uint32_t g_w1t[(size_t)E_*HD_*DIM_];   /* W1^T [e][c][k] (plain)      */
__device__ uint32_t g_w2t[(size_t)E_*DIM_*HD_];   /* W2^T [e][c][k], KPERM'd     */

__device__ __forceinline__ uint32_t f2tf32(float f) {
    uint32_t r;
    asm("cvt.rna.tf32.f32 %0, %1;" : "=r"(r) : "f"(f));
    return r;
}

__device__ __forceinline__ void mma_tf32(float* d, const uint32_t* a, const uint32_t* b) {
    asm("mma.sync.aligned.m16n8k8.row.col.f32.tf32.tf32.f32 "
        "{%0,%1,%2,%3}, {%4,%5,%6,%7}, {%8,%9}, {%0,%1,%2,%3};"
        : "+f"(d[0]), "+f"(d[1]), "+f"(d[2]), "+f"(d[3])
        : "r"(a[0]), "r"(a[1]), "r"(a[2]), "r"(a[3]), "r"(b[0]), "r"(b[1]));
}

__device__ __forceinline__ void red_add_v2(float* addr, float a, float b) {
    asm volatile("red.global.add.v2.f32 [%0], {%1, %2};"
                 :: "l"(addr), "f"(a), "f"(b) : "memory");
}

__device__ __forceinline__ void cp_async16(uint32_t dst_smem, const void* src) {
    asm volatile("cp.async.cg.shared.global [%0], [%1], 16;"
                 :: "r"(dst_smem), "l"(src));
}
__device__ __forceinline__ void cp_commit() {
    asm volatile("cp.async.commit_group;");
}
template<int N> __device__ __forceinline__ void cp_wait() {
    asm volatile("cp.async.wait_group %0;" :: "n"(N));
}

/* ===== prep: gate+preconvert (blocks 0-1023) | kv (1024-1407) ===== */
__global__ void prep_kernel(const float* __restrict__ x,
                            const float* __restrict__ Wg,
                            const float* __restrict__ W1,
                            const float* __restrict__ W2,
                            const float* __restrict__ Wkv,
                            const float* __restrict__ bkv,
                            const int*   __restrict__ task_p) {
    __shared__ float sbuf[4352];
    __shared__ float sme[E_];
    __shared__ float szv;
    __shared__ int   scnt[E_];
    __shared__ int   sbase[E_];
    int bx  = blockIdx.x;
    int tid = threadIdx.x;

    if (bx < 1024) {
        /* ------------------- gating ------------------- */
        int warp = tid >> 5, lane = tid & 31;
        int t = bx * 8 + warp;
        if (tid < E_) { sme[tid] = 0.f; scnt[tid] = 0; }
        if (tid == 0) szv = 0.f;
        __syncthreads();

        int task = *task_p;
        const float* wg = Wg + (size_t)task * DIM_ * E_;
        const float* xr = x + (size_t)t * DIM_;

        float acc = 0.f;
        if (lane < E_) {
            #pragma unroll 4
            for (int d = 0; d < DIM_; d++) acc += xr[d] * wg[d * E_ + lane];
        }
        float logit = (lane < E_) ? acc : -1e30f;

        float m = logit;
        #pragma unroll
        for (int o = 16; o >= 1; o >>= 1) m = fmaxf(m, __shfl_xor_sync(0xffffffffu, m, o));
        float p = (lane < E_) ? expf(logit - m) : 0.f;
        float s = p;
        #pragma unroll
        for (int o = 16; o >= 1; o >>= 1) s += __shfl_xor_sync(0xffffffffu, s, o);
        float prob = p / s;
        float lse = m + logf(s);
        if (lane == 0) atomicAdd(&szv, lse * lse);
        if (lane < E_) atomicAdd(&sme[lane], prob);

        float val = (lane < E_) ? prob : -1.f;
        float sel_g = 0.f; int sel_e = 0;
        #pragma unroll
        for (int it = 0; it < H_; it++) {
            float mm = val;
            #pragma unroll
            for (int o = 16; o >= 1; o >>= 1)
                mm = fmaxf(mm, __shfl_xor_sync(0xffffffffu, mm, o));
            unsigned msk = __ballot_sync(0xffffffffu, val == mm);
            int src = __ffs(msk) - 1;
            if (lane == src) val = -1.f;
            if (lane == it) { sel_e = src; sel_g = mm; }
        }
        float gv = (lane < H_) ? sel_g : 0.f;
        #pragma unroll
        for (int o = 16; o >= 1; o >>= 1) gv += __shfl_xor_sync(0xffffffffu, gv, o);
        float denom = gv + 1e-6f;

        int pos = 0;
        if (lane < H_) pos = atomicAdd(&scnt[sel_e], 1);
        __syncthreads();
        if (tid < E_) sbase[tid] = atomicAdd(&g_ecount[tid], scnt[tid]);
        __syncthreads();
        if (lane < H_) {
            int a = t * H_ + lane;
            g_gate[a] = sel_g / denom;
            g_elist[sel_e * NA + sbase[sel_e] + pos] = a;
        }
        if (tid < E_) atomicAdd(&g_me[tid], sme[tid]);
        if (tid == 0) atomicAdd(&g_z, szv);

        /* ---- pre-convert x -> g_xt (plain) ---- */
        {
            const float4* xin = (const float4*)x;
            uint4* xout = (uint4*)g_xt;
            int base4 = bx * 1536;
            for (int i = tid; i < 1536; i += 256) {
                float4 v = xin[base4 + i];
                uint4 u;
                u.x = f2tf32(v.x); u.y = f2tf32(v.y);
                u.z = f2tf32(v.z); u.w = f2tf32(v.w);
                xout[base4 + i] = u;
            }
        }

        /* ---- W1 -> g_w1t [e][c][k] plain (1728 tiles) ---- */
        float (*tile)[33] = (float(*)[33])sbuf;
        int ty = tid >> 5, tx8 = tid & 31;
        for (int tix = bx; tix < 1728; tix += 1024) {
            int e  = tix / 72;
            int rem = tix % 72;
            int kt = rem / 3, ct = rem % 3;
            __syncthreads();
            for (int r = ty; r < 32; r += 8)
                tile[r][tx8] = W1[((size_t)e * DIM_ + kt * 32 + r) * HD_ + ct * 32 + tx8];
            __syncthreads();
            for (int r = ty; r < 32; r += 8)
                g_w1t[((size_t)e * HD_ + ct * 32 + r) * DIM_ + kt * 32 + tx8] =
                    f2tf32(tile[tx8][r]);
        }

        /* ---- W2 -> g_w2t [e][c][k] KPERM'd (1728 tiles) ---- */
        int kp = KPERM(tx8);
        for (int tix = bx; tix < 1728; tix += 1024) {
            int e  = tix / 72;
            int rem = tix % 72;
            int kt = rem / 24, ct = rem % 24;
            __syncthreads();
            for (int r = ty; r < 32; r += 8)
                tile[r][tx8] = W2[((size_t)e * HD_ + kt * 32 + r) * DIM_ + ct * 32 + tx8];
            __syncthreads();
            for (int r = ty; r < 32; r += 8)
                g_w2t[((size_t)e * DIM_ + ct * 32 + r) * HD_ + kt * 32 + kp] =
                    f2tf32(tile[tx8][r]);
        }
    } else {
        /* ------ kv projection (R12 form): 64x64 tiles, grid part 1024-1407 ------ */
        float (*xsT)[68] = (float(*)[68])sbuf;
        float (*ws)[68]  = (float(*)[68])(sbuf + 32 * 68);
        int i = bx - 1024;
        int r0 = (i & 127) * 64;
        int c0 = (i >> 7) * 64;
        int ty = tid >> 4, tx = tid & 15;
        float acc[4][4] = {};

        for (int k0 = 0; k0 < DIM_; k0 += 32) {
            for (int ii = tid; ii < 64 * 32; ii += 256) {
                int r = ii >> 5, k = ii & 31;
                xsT[k][r] = x[(size_t)(r0 + r) * DIM_ + k0 + k];
            }
            for (int ii = tid; ii < 32 * 64; ii += 256) {
                int k = ii >> 6, c = ii & 63;
                ws[k][c] = Wkv[(size_t)(k0 + k) * (2 * HD_) + c0 + c];
            }
            __syncthreads();
            #pragma unroll
            for (int k = 0; k < 32; k++) {
                float4 a4 = *(const float4*)&xsT[k][ty * 4];
                float4 b4 = *(const float4*)&ws[k][tx * 4];
                float av[4] = {a4.x, a4.y, a4.z, a4.w};
                float bv[4] = {b4.x, b4.y, b4.z, b4.w};
                #pragma unroll
                for (int ri = 0; ri < 4; ri++)
                    #pragma unroll
                    for (int cj = 0; cj < 4; cj++) acc[ri][cj] += av[ri] * bv[cj];
            }
            __syncthreads();
        }
        #pragma unroll
        for (int ri = 0; ri < 4; ri++) {
            int r = r0 + ty * 4 + ri;
            #pragma unroll
            for (int cj = 0; cj < 4; cj++) {
                int c = c0 + tx * 4 + cj;
                uint32_t v = f2tf32(acc[ri][cj] + bkv[c]);
                if (c < HD_) g_kt[(size_t)r * HD_ + c]          = v;
                else         g_vt[(size_t)r * HD_ + (c - HD_)]  = v;
            }
        }
    }
}

/* ------------------------ zero output (for atomic reduce) ------------------- */
__global__ void zero_out_kernel(float* __restrict__ out, int n) {
    int tid = threadIdx.x;
    float4* o4 = (float4*)out;
    const int n4 = NT * DIM_ / 4;
    for (int i = blockIdx.x * 256 + tid; i < n4; i += 256 * 256)
        o4[i] = make_float4(0.f, 0.f, 0.f, 0.f);
    for (int i = NT * DIM_ + blockIdx.x * 256 + tid; i < n; i += 256 * 256)
        out[i] = 0.f;
}

/* ------- grouped q projection (R12 form): cp.async dbuf tf32 mma ------------ */
#define Q_SMEM_WORDS (2*128*36 + 2*96*36)
__global__ void __launch_bounds__(256) q_tc_kernel() {
    int e = blockIdx.y;
    int count = g_ecount[e];
    int base = blockIdx.x * 128;
    if (base >= count) return;

    extern __shared__ uint32_t qsm[];
    uint32_t* xs = qsm;
    uint32_t* ws = qsm + 2 * 128 * 36;
    __shared__ int s_a[128];
    int tid = threadIdx.x;
    if (tid < 128) {
        int idx = base + tid; if (idx >= count) idx = count - 1;
        s_a[tid] = g_elist[e * NA + idx];
    }
    __syncthreads();

    uint32_t xs_smem = (uint32_t)__cvta_generic_to_shared(xs);
    uint32_t ws_smem = (uint32_t)__cvta_generic_to_shared(ws);
    const uint32_t* w1t = g_w1t + (size_t)e * HD_ * DIM_;

    int wid = tid >> 5, lane = tid & 31;
    int g = lane >> 2, tig = lane & 3;
    int row_a0 = wid * 16 + g, row_a1 = row_a0 + 8;

    float acc[12][4];
    #pragma unroll
    for (int nn = 0; nn < 12; nn++)
        #pragma unroll
        for (int r = 0; r < 4; r++) acc[nn][r] = 0.f;

    auto fill = [&](int bi, int k0) {
        uint32_t xb = xs_smem + bi * (128 * 36 * 4);
        uint32_t wb = ws_smem + bi * (96 * 36 * 4);
        #pragma unroll
        for (int j = 0; j < 4; j++) {
            int item = tid + 256 * j;
            int r = item >> 3, seg = item & 7;
            int tok = s_a[r] >> 3;
            cp_async16(xb + (r * 36 + seg * 4) * 4,
                       g_xt + (size_t)tok * DIM_ + k0 + seg * 4);
        }
        #pragma unroll
        for (int j = 0; j < 3; j++) {
            int item = tid + 256 * j;
            int c = item >> 3, seg = item & 7;
            cp_async16(wb + (c * 36 + seg * 4) * 4,
                       w1t + (size_t)c * DIM_ + k0 + seg * 4);
        }
        cp_commit();
    };

    fill(0, 0);
    for (int c = 0; c < 24; c++) {
        if (c < 23) fill((c + 1) & 1, (c + 1) * 32);
        if (c < 23) cp_wait<1>(); else cp_wait<0>();
        __syncthreads();
        uint32_t* xsb = xs + (c & 1) * 128 * 36;
        uint32_t* wsb = ws + (c & 1) * 96 * 36;
        #pragma unroll
        for (int kk = 0; kk < 4; kk++) {
            uint32_t a[4];
            a[0] = xsb[row_a0 * 36 + kk * 8 + tig];
            a[1] = xsb[row_a1 * 36 + kk * 8 + tig];
            a[2] = xsb[row_a0 * 36 + kk * 8 + tig + 4];
            a[3] = xsb[row_a1 * 36 + kk * 8 + tig + 4];
            #pragma unroll
            for (int nn = 0; nn < 12; nn++) {
                uint32_t bb[2];
                bb[0] = wsb[(nn * 8 + g) * 36 + kk * 8 + tig];
                bb[1] = wsb[(nn * 8 + g) * 36 + kk * 8 + tig + 4];
                mma_tf32(acc[nn], a, bb);
            }
        }
        __syncthreads();
    }

    bool ok0 = (base + row_a0 < count), ok1 = (base + row_a1 < count);
    int a0 = s_a[row_a0], a1 = s_a[row_a1];
    #pragma unroll
    for (int nn = 0; nn < 12; nn++) {
        int c = nn * 8 + tig * 2;
        if (ok0) {
            g_qt[(size_t)a0 * HD_ + c]     = f2tf32(acc[nn][0] * SCALE_);
            g_qt[(size_t)a0 * HD_ + c + 1] = f2tf32(acc[nn][1] * SCALE_);
        }
        if (ok1) {
            g_qt[(size_t)a1 * HD_ + c]     = f2tf32(acc[nn][2] * SCALE_);
            g_qt[(size_t)a1 * HD_ + c + 1] = f2tf32(acc[nn][3] * SCALE_);
        }
    }
}

/* ------- fused flash attention (R12 form); epilogue writes KPERM'd g_ot ----- */
#define QS_STRIDE 100
#define KS_STRIDE 100
#define VS_STRIDE 104
#define PS_STRIDE 68
#define ATTN_SMEM_WORDS (128*QS_STRIDE + 2*64*KS_STRIDE + 2*64*VS_STRIDE + 8*16*PS_STRIDE)

__global__ void __launch_bounds__(256, 1) attn_tc_kernel() {
    extern __shared__ uint32_t smu[];
    uint32_t* qs = smu;                                    /* [128][100]   */
    uint32_t* ks = qs + 128 * QS_STRIDE;                   /* [2][64][100] */
    uint32_t* vs = ks + 2 * 64 * KS_STRIDE;                /* [2][64][104] */
    uint32_t* ps = vs + 2 * 64 * VS_STRIDE;                /* [8][16][68]  */

    int it = blockIdx.x, bh = blockIdx.y;
    int b = bh >> 3, h = bh & 7;
    int i0 = it * 128;
    int tid  = threadIdx.x;
    int wid  = tid >> 5;
    int lane = tid & 31;
    int g    = lane >> 2;
    int tig  = lane & 3;
    uint32_t* pw = ps + wid * 16 * PS_STRIDE;

    uint32_t qs_s = (uint32_t)__cvta_generic_to_shared(qs);
    uint32_t ks_s = (uint32_t)__cvta_generic_to_shared(ks);
    uint32_t vs_s = (uint32_t)__cvta_generic_to_shared(vs);

    #pragma unroll
    for (int j = 0; j < 12; j++) {
        int item = tid + 256 * j;
        int r = item / 24, seg = item % 24;
        cp_async16(qs_s + (r * QS_STRIDE + seg * 4) * 4,
                   g_qt + ((size_t)(b * N_ + i0 + r) * H_ + h) * HD_ + seg * 4);
    }
    cp_commit();

    auto fill_kv = [&](int bi, int jt) {
        int j0 = jt * 64;
        uint32_t kb = ks_s + bi * (64 * KS_STRIDE * 4);
        uint32_t vb = vs_s + bi * (64 * VS_STRIDE * 4);
        #pragma unroll
        for (int j = 0; j < 6; j++) {
            int item = tid + 256 * j;
            int r = item / 24, seg = item % 24;
            size_t src = (size_t)(b * N_ + j0 + r) * HD_ + seg * 4;
            cp_async16(kb + (r * KS_STRIDE + seg * 4) * 4, g_kt + src);
            cp_async16(vb + (r * VS_STRIDE + seg * 4) * 4, g_vt + src);
        }
        cp_commit();
    };
    fill_kv(0, 0);

    float m0 = -1e30f, m1 = -1e30f, l0 = 0.f, l1 = 0.f;
    float o_acc[12][4];
    #pragma unroll
    for (int nn = 0; nn < 12; nn++)
        #pragma unroll
        for (int r = 0; r < 4; r++) o_acc[nn][r] = 0.f;

    int row_a0 = wid * 16 + g;
    int row_a1 = wid * 16 + g + 8;

    for (int jt = 0; jt < 16; jt++) {
        cp_wait<0>();
        __syncthreads();
        if (jt < 15) fill_kv((jt + 1) & 1, jt + 1);
        uint32_t* ksb = ks + (jt & 1) * 64 * KS_STRIDE;
        uint32_t* vsb = vs + (jt & 1) * 64 * VS_STRIDE;

        float sv[8][4];
        #pragma unroll
        for (int nn = 0; nn < 8; nn++)
            #pragma unroll
            for (int r = 0; r < 4; r++) sv[nn][r] = 0.f;

        #pragma unroll
        for (int kk = 0; kk < 12; kk++) {
            uint32_t a[4];
            a[0] = qs[row_a0 * QS_STRIDE + kk * 8 + tig];
            a[1] = qs[row_a1 * QS_STRIDE + kk * 8 + tig];
            a[2] = qs[row_a0 * QS_STRIDE + kk * 8 + tig + 4];
            a[3] = qs[row_a1 * QS_STRIDE + kk * 8 + tig + 4];
            #pragma unroll
            for (int nn = 0; nn < 8; nn++) {
                uint32_t bb[2];
                bb[0] = ksb[(nn * 8 + g) * KS_STRIDE + kk * 8 + tig];
                bb[1] = ksb[(nn * 8 + g) * KS_STRIDE + kk * 8 + tig + 4];
                mma_tf32(sv[nn], a, bb);
            }
        }

        float rmax0 = -1e30f, rmax1 = -1e30f;
        #pragma unroll
        for (int nn = 0; nn < 8; nn++) {
            rmax0 = fmaxf(rmax0, fmaxf(sv[nn][0], sv[nn][1]));
            rmax1 = fmaxf(rmax1, fmaxf(sv[nn][2], sv[nn][3]));
        }
        #pragma unroll
        for (int o = 1; o <= 2; o <<= 1) {
            rmax0 = fmaxf(rmax0, __shfl_xor_sync(0xffffffffu, rmax0, o));
            rmax1 = fmaxf(rmax1, __shfl_xor_sync(0xffffffffu, rmax1, o));
        }
        float nm0 = fmaxf(m0, rmax0), nm1 = fmaxf(m1, rmax1);
        float corr0 = __expf(m0 - nm0), corr1 = __expf(m1 - nm1);
        float rs0 = 0.f, rs1 = 0.f;
        #pragma unroll
        for (int nn = 0; nn < 8; nn++) {
            float p00 = __expf(sv[nn][0] - nm0);
            float p01 = __expf(sv[nn][1] - nm0);
            float p10 = __expf(sv[nn][2] - nm1);
            float p11 = __expf(sv[nn][3] - nm1);
            rs0 += p00 + p01; rs1 += p10 + p11;
            int c = nn * 8 + tig * 2;
            pw[g * PS_STRIDE + c]           = f2tf32(p00);
            pw[g * PS_STRIDE + c + 1]       = f2tf32(p01);
            pw[(g + 8) * PS_STRIDE + c]     = f2tf32(p10);
            pw[(g + 8) * PS_STRIDE + c + 1] = f2tf32(p11);
        }
        #pragma unroll
        for (int o = 1; o <= 2; o <<= 1) {
            rs0 += __shfl_xor_sync(0xffffffffu, rs0, o);
            rs1 += __shfl_xor_sync(0xffffffffu, rs1, o);
        }
        l0 = l0 * corr0 + rs0;  m0 = nm0;
        l1 = l1 * corr1 + rs1;  m1 = nm1;
        #pragma unroll
        for (int nn = 0; nn < 12; nn++) {
            o_acc[nn][0] *= corr0; o_acc[nn][1] *= corr0;
            o_acc[nn][2] *= corr1; o_acc[nn][3] *= corr1;
        }
        __syncwarp();

        #pragma unroll
        for (int kk = 0; kk < 8; kk++) {
            uint32_t a[4];
            a[0] = pw[g * PS_STRIDE + kk * 8 + tig];
            a[1] = pw[(g + 8) * PS_STRIDE + kk * 8 + tig];
            a[2] = pw[g * PS_STRIDE + kk * 8 + tig + 4];
            a[3] = pw[(g + 8) * PS_STRIDE + kk * 8 + tig + 4];
            #pragma unroll
            for (int nn = 0; nn < 12; nn++) {
                uint32_t bb[2];
                bb[0] = vsb[(kk * 8 + tig) * VS_STRIDE + nn * 8 + g];
                bb[1] = vsb[(kk * 8 + tig + 4) * VS_STRIDE + nn * 8 + g];
                mma_tf32(o_acc[nn], a, bb);
            }
        }
        __syncwarp();
    }

    /* epilogue: gate-weighted tf32 o rows, KPERM'd for the reduce kernel */
    float inv0 = 1.f / l0, inv1 = 1.f / l1;
    int tok0 = b * N_ + i0 + row_a0;
    int tok1 = b * N_ + i0 + row_a1;
    int a0 = tok0 * H_ + h, a1 = tok1 * H_ + h;
    float ga0 = g_gate[a0], ga1 = g_gate[a1];
    #pragma unroll
    for (int nn = 0; nn < 12; nn++) {
        int c = nn * 8 + tig * 2;
        g_ot[(size_t)a0 * HD_ + KPERM(c)]     = f2tf32(ga0 * (o_acc[nn][0] * inv0));
        g_ot[(size_t)a0 * HD_ + KPERM(c + 1)] = f2tf32(ga0 * (o_acc[nn][1] * inv0));
        g_ot[(size_t)a1 * HD_ + KPERM(c)]     = f2tf32(ga1 * (o_acc[nn][2] * inv1));
        g_ot[(size_t)a1 * HD_ + KPERM(c + 1)] = f2tf32(ga1 * (o_acc[nn][3] * inv1));
    }
}

/* -- grouped reduce (R15 form, measured 118.5us): stride 104, LDS.64 --------- */
#define RD_STR 104
#define RED_SMEM_WORDS (128*RD_STR + 2*48*RD_STR)   /* 93184 bytes */
__global__ void __launch_bounds__(256) red_tc_kernel(float* __restrict__ out) {
    int e = blockIdx.y;
    int count = g_ecount[e];
    int base = blockIdx.x * 128;
    if (base >= count) return;

    extern __shared__ uint32_t rsm[];
    uint32_t* osT = rsm;                      /* [128][104]   */
    uint32_t* w2T = rsm + 128 * RD_STR;       /* [2][48][104] */
    __shared__ int s_a[128];

    int tid = threadIdx.x;
    if (tid < 128) {
        int idx = base + tid; if (idx >= count) idx = count - 1;
        s_a[tid] = g_elist[e * NA + idx];
    }
    __syncthreads();

    uint32_t osT_s = (uint32_t)__cvta_generic_to_shared(osT);
    uint32_t w2T_s = (uint32_t)__cvta_generic_to_shared(w2T);
    const uint32_t* w2te = g_w2t + (size_t)e * DIM_ * HD_;

    #pragma unroll
    for (int j = 0; j < 12; j++) {
        int item = tid + 256 * j;
        int r = item / 24, seg = item % 24;
        int a = s_a[r];
        cp_async16(osT_s + (r * RD_STR + seg * 4) * 4,
                   g_ot + (size_t)a * HD_ + seg * 4);
    }

    auto fill_w2 = [&](int bi, int ct) {
        uint32_t wb = w2T_s + bi * (48 * RD_STR * 4);
        const uint32_t* src = w2te + (size_t)(ct * 48) * HD_;
        #pragma unroll
        for (int j = 0; j < 5; j++) {
            int item = tid + 256 * j;
            if (item < 1152) {
                int c = item / 24, seg = item % 24;
                cp_async16(wb + (c * RD_STR + seg * 4) * 4,
                           src + (size_t)c * HD_ + seg * 4);
            }
        }
        cp_commit();
    };
    fill_w2(0, 0);

    int wid = tid >> 5, lane = tid & 31;
    int g = lane >> 2, tig = lane & 3;
    int row_a0 = wid * 16 + g, row_a1 = row_a0 + 8;
    bool ok0 = (base + row_a0 < count), ok1 = (base + row_a1 < count);
    int t0 = s_a[row_a0] >> 3, t1 = s_a[row_a1] >> 3;

    for (int ct = 0; ct < 16; ct++) {
        if (ct < 15) fill_w2((ct + 1) & 1, ct + 1);
        if (ct < 15) cp_wait<1>(); else cp_wait<0>();
        __syncthreads();
        uint32_t* wsb = w2T + (ct & 1) * 48 * RD_STR;

        float acc[6][4];
        #pragma unroll
        for (int nn = 0; nn < 6; nn++)
            #pragma unroll
            for (int r = 0; r < 4; r++) acc[nn][r] = 0.f;

        #pragma unroll
        for (int kk = 0; kk < 12; kk++) {
            uint32_t a[4];
            uint2 oa0 = *(const uint2*)&osT[row_a0 * RD_STR + kk * 8 + 2 * tig];
            uint2 oa1 = *(const uint2*)&osT[row_a1 * RD_STR + kk * 8 + 2 * tig];
            a[0] = oa0.x; a[2] = oa0.y;
            a[1] = oa1.x; a[3] = oa1.y;
            #pragma unroll
            for (int nn = 0; nn < 6; nn++) {
                uint2 wb_ = *(const uint2*)&wsb[(nn * 8 + g) * RD_STR + kk * 8 + 2 * tig];
                uint32_t bb[2] = {wb_.x, wb_.y};
                mma_tf32(acc[nn], a, bb);
            }
        }

        #pragma unroll
        for (int nn = 0; nn < 6; nn++) {
            int c = ct * 48 + nn * 8 + tig * 2;
            if (ok0) red_add_v2(&out[(size_t)t0 * DIM_ + c], acc[nn][0], acc[nn][1]);
            if (ok1) red_add_v2(&out[(size_t)t1 * DIM_ + c], acc[nn][2], acc[nn][3]);
        }
        __syncthreads();
    }
}

/* ------------- aux loss + restore zeroed gating state for next run ---------- */
__global__ void aux_kernel(float* __restrict__ out, int out_size) {
    int tid = threadIdx.x;
    if (tid == 0) {
        float mesum = 0.f;
        for (int e = 0; e < E_; e++) mesum += g_me[e];
        float sw = 0.f;
        for (int e = 0; e < E_; e++)
            sw += (g_me[e] / mesum) * ((float)g_ecount[e] / (float)NA);
        sw *= (float)E_;
        float z = g_z / (float)NT;
        float aux = 0.1f * sw + 0.001f * z;
        if (out_size > NT * DIM_) out[out_size - 1] = aux;
    }
    __syncwarp();
    if (tid < E_) { g_me[tid] = 0.f; g_ecount[tid] = 0; }
    if (tid == 0) g_z = 0.f;
}

/* -------------------------------- launch ------------------------------------ */
extern "C" void kernel_launch(void* const* d_in, const int* in_sizes, int n_in,
                              void* d_out, int out_size) {
    const float* x    = (const float*)d_in[0];
    const float* Wg   = (const float*)d_in[1];
    const float* W1   = (const float*)d_in[2];
    const float* W2   = (const float*)d_in[3];
    const float* Wkv  = (const float*)d_in[4];
    const float* bkv  = (const float*)d_in[5];
    const int*   task = (const int*)d_in[6];
    float* out = (float*)d_out;

    cudaFuncSetAttribute(attn_tc_kernel,
                         cudaFuncAttributeMaxDynamicSharedMemorySize,
                         ATTN_SMEM_WORDS * (int)sizeof(uint32_t));
    cudaFuncSetAttribute(red_tc_kernel,
                         cudaFuncAttributeMaxDynamicSharedMemorySize,
                         RED_SMEM_WORDS * (int)sizeof(uint32_t));
    cudaFuncSetAttribute(q_tc_kernel,
                         cudaFuncAttributeMaxDynamicSharedMemorySize,
                         Q_SMEM_WORDS * (int)sizeof(uint32_t));

    prep_kernel<<<1408, 256>>>(x, Wg, W1, W2, Wkv, bkv, task);               /* #1 */
    q_tc_kernel<<<dim3(64, E_), 256, Q_SMEM_WORDS * sizeof(uint32_t)>>>();   /* #2 */
    zero_out_kernel<<<256, 256>>>(out, out_size);                            /* #3 */
    attn_tc_kernel<<<dim3(8, B_ * H_), 256,
                     ATTN_SMEM_WORDS * sizeof(uint32_t)>>>();                /* #4 */
    red_tc_kernel<<<dim3(64, E_), 256,
                    RED_SMEM_WORDS * sizeof(uint32_t)>>>(out);               /* #5 */
    aux_kernel<<<1, 32>>>(out, out_size);                                    /* #6 */
}

// round 17
// speedup vs baseline: 1.4685x; 1.0669x over previous
#include <cuda_runtime.h>
#include <math.h>
#include <stdint.h>

#define B_    8
#define N_    1024
#define DIM_  768
#define H_    8
#define HD_   96
#define E_    24
#define NT    (B_*N_)      /* 8192 tokens */
#define NA    (NT*H_)      /* 65536 assignments */
#define SCALE_ 0.10206207261596575f  /* 96^-0.5 */

/* k-group permutation: pairs (i,i+4) -> adjacent (2i,2i+1) within 8-groups */
#define KPERM(d) (((d) & ~7) | (((d) & 3) << 1) | (((d) >> 2) & 1))

/* ------------------------- scratch (device globals) ------------------------- */
__device__ float    g_gate[NA];
__device__ float    g_me[E_];        /* zero-init; aux re-zeroes each run */
__device__ float    g_z;
__device__ int      g_ecount[E_];
__device__ int      g_elist[E_*NA];
__device__ uint32_t g_kt[NT*HD_];                 /* k tf32, KPERM'd             */
__device__ uint32_t g_vtT[NT*HD_];                /* v tf32 ^T [b][d][j], j-KPERM */
__device__ uint32_t g_qt[(size_t)NA*HD_];         /* q*scale tf32, KPERM'd       */
__device__ uint32_t g_ot[(size_t)NA*HD_];         /* gate*o tf32, KPERM'd        */
__device__ uint32_t g_xt[(size_t)NT*DIM_];        /* x tf32, KPERM'd             */
__device__ uint32_t g_w1t[(size_t)E_*HD_*DIM_];   /* W1^T [e][c][k], KPERM'd     */
__device__ uint32_t g_w2t[(size_t)E_*DIM_*HD_];   /* W2^T [e][c][k], KPERM'd     */

__device__ __forceinline__ uint32_t f2tf32(float f) {
    uint32_t r;
    asm("cvt.rna.tf32.f32 %0, %1;" : "=r"(r) : "f"(f));
    return r;
}

__device__ __forceinline__ void mma_tf32(float* d, const uint32_t* a, const uint32_t* b) {
    asm("mma.sync.aligned.m16n8k8.row.col.f32.tf32.tf32.f32 "
        "{%0,%1,%2,%3}, {%4,%5,%6,%7}, {%8,%9}, {%0,%1,%2,%3};"
        : "+f"(d[0]), "+f"(d[1]), "+f"(d[2]), "+f"(d[3])
        : "r"(a[0]), "r"(a[1]), "r"(a[2]), "r"(a[3]), "r"(b[0]), "r"(b[1]));
}

__device__ __forceinline__ void red_add_v2(float* addr, float a, float b) {
    asm volatile("red.global.add.v2.f32 [%0], {%1, %2};"
                 :: "l"(addr), "f"(a), "f"(b) : "memory");
}

__device__ __forceinline__ void cp_async16(uint32_t dst_smem, const void* src) {
    asm volatile("cp.async.cg.shared.global [%0], [%1], 16;"
                 :: "r"(dst_smem), "l"(src));
}
__device__ __forceinline__ void cp_commit() {
    asm volatile("cp.async.commit_group;");
}
template<int N> __device__ __forceinline__ void cp_wait() {
    asm volatile("cp.async.wait_group %0;" :: "n"(N));
}

/* ===== prep: gate+preconvert (blocks 0-1023) | kv (1024-1407) ===== */
__global__ void prep_kernel(const float* __restrict__ x,
                            const float* __restrict__ Wg,
                            const float* __restrict__ W1,
                            const float* __restrict__ W2,
                            const float* __restrict__ Wkv,
                            const float* __restrict__ bkv,
                            const int*   __restrict__ task_p) {
    __shared__ float sbuf[4352];
    __shared__ float sme[E_];
    __shared__ float szv;
    __shared__ int   scnt[E_];
    __shared__ int   sbase[E_];
    int bx  = blockIdx.x;
    int tid = threadIdx.x;

    if (bx < 1024) {
        /* ------------------- gating ------------------- */
        int warp = tid >> 5, lane = tid & 31;
        int t = bx * 8 + warp;
        if (tid < E_) { sme[tid] = 0.f; scnt[tid] = 0; }
        if (tid == 0) szv = 0.f;
        __syncthreads();

        int task = *task_p;
        const float* wg = Wg + (size_t)task * DIM_ * E_;
        const float* xr = x + (size_t)t * DIM_;

        float acc = 0.f;
        if (lane < E_) {
            #pragma unroll 4
            for (int d = 0; d < DIM_; d++) acc += xr[d] * wg[d * E_ + lane];
        }
        float logit = (lane < E_) ? acc : -1e30f;

        float m = logit;
        #pragma unroll
        for (int o = 16; o >= 1; o >>= 1) m = fmaxf(m, __shfl_xor_sync(0xffffffffu, m, o));
        float p = (lane < E_) ? expf(logit - m) : 0.f;
        float s = p;
        #pragma unroll
        for (int o = 16; o >= 1; o >>= 1) s += __shfl_xor_sync(0xffffffffu, s, o);
        float prob = p / s;
        float lse = m + logf(s);
        if (lane == 0) atomicAdd(&szv, lse * lse);
        if (lane < E_) atomicAdd(&sme[lane], prob);

        float val = (lane < E_) ? prob : -1.f;
        float sel_g = 0.f; int sel_e = 0;
        #pragma unroll
        for (int it = 0; it < H_; it++) {
            float mm = val;
            #pragma unroll
            for (int o = 16; o >= 1; o >>= 1)
                mm = fmaxf(mm, __shfl_xor_sync(0xffffffffu, mm, o));
            unsigned msk = __ballot_sync(0xffffffffu, val == mm);
            int src = __ffs(msk) - 1;
            if (lane == src) val = -1.f;
            if (lane == it) { sel_e = src; sel_g = mm; }
        }
        float gv = (lane < H_) ? sel_g : 0.f;
        #pragma unroll
        for (int o = 16; o >= 1; o >>= 1) gv += __shfl_xor_sync(0xffffffffu, gv, o);
        float denom = gv + 1e-6f;

        int pos = 0;
        if (lane < H_) pos = atomicAdd(&scnt[sel_e], 1);
        __syncthreads();
        if (tid < E_) sbase[tid] = atomicAdd(&g_ecount[tid], scnt[tid]);
        __syncthreads();
        if (lane < H_) {
            int a = t * H_ + lane;
            g_gate[a] = sel_g / denom;
            g_elist[sel_e * NA + sbase[sel_e] + pos] = a;
        }
        if (tid < E_) atomicAdd(&g_me[tid], sme[tid]);
        if (tid == 0) atomicAdd(&g_z, szv);

        /* ---- pre-convert x -> g_xt (tf32, KPERM'd per 8-group) ---- */
        {
            const float4* xin = (const float4*)x;
            uint4* xout = (uint4*)g_xt;
            int gbase = bx * 768;              /* 8-word groups per block */
            for (int i = tid; i < 768; i += 256) {
                int gi = gbase + i;
                float4 in0 = xin[2 * gi], in1 = xin[2 * gi + 1];
                uint4 lo, hi;
                lo.x = f2tf32(in0.x); lo.y = f2tf32(in1.x);
                lo.z = f2tf32(in0.y); lo.w = f2tf32(in1.y);
                hi.x = f2tf32(in0.z); hi.y = f2tf32(in1.z);
                hi.z = f2tf32(in0.w); hi.w = f2tf32(in1.w);
                xout[2 * gi]     = lo;
                xout[2 * gi + 1] = hi;
            }
        }

        /* ---- W1 -> g_w1t [e][c][k] KPERM'd (1728 tiles) ---- */
        float (*tile)[33] = (float(*)[33])sbuf;
        int ty = tid >> 5, tx8 = tid & 31;
        int kp = KPERM(tx8);
        for (int tix = bx; tix < 1728; tix += 1024) {
            int e  = tix / 72;
            int rem = tix % 72;
            int kt = rem / 3, ct = rem % 3;
            __syncthreads();
            for (int r = ty; r < 32; r += 8)
                tile[r][tx8] = W1[((size_t)e * DIM_ + kt * 32 + r) * HD_ + ct * 32 + tx8];
            __syncthreads();
            for (int r = ty; r < 32; r += 8)
                g_w1t[((size_t)e * HD_ + ct * 32 + r) * DIM_ + kt * 32 + kp] =
                    f2tf32(tile[tx8][r]);
        }

        /* ---- W2 -> g_w2t [e][c][k] KPERM'd (1728 tiles) ---- */
        for (int tix = bx; tix < 1728; tix += 1024) {
            int e  = tix / 72;
            int rem = tix % 72;
            int kt = rem / 24, ct = rem % 24;
            __syncthreads();
            for (int r = ty; r < 32; r += 8)
                tile[r][tx8] = W2[((size_t)e * HD_ + kt * 32 + r) * DIM_ + ct * 32 + tx8];
            __syncthreads();
            for (int r = ty; r < 32; r += 8)
                g_w2t[((size_t)e * DIM_ + ct * 32 + r) * HD_ + kt * 32 + kp] =
                    f2tf32(tile[tx8][r]);
        }
    } else {
        /* -- kv projection (R12 GEMM form); outputs KPERM'd k, transposed v -- */
        float (*xsT)[68] = (float(*)[68])sbuf;
        float (*ws)[68]  = (float(*)[68])(sbuf + 32 * 68);
        int i = bx - 1024;
        int r0 = (i & 127) * 64;
        int c0 = (i >> 7) * 64;
        int ty = tid >> 4, tx = tid & 15;
        float acc[4][4] = {};

        for (int k0 = 0; k0 < DIM_; k0 += 32) {
            for (int ii = tid; ii < 64 * 32; ii += 256) {
                int r = ii >> 5, k = ii & 31;
                xsT[k][r] = x[(size_t)(r0 + r) * DIM_ + k0 + k];
            }
            for (int ii = tid; ii < 32 * 64; ii += 256) {
                int k = ii >> 6, c = ii & 63;
                ws[k][c] = Wkv[(size_t)(k0 + k) * (2 * HD_) + c0 + c];
            }
            __syncthreads();
            #pragma unroll
            for (int k = 0; k < 32; k++) {
                float4 a4 = *(const float4*)&xsT[k][ty * 4];
                float4 b4 = *(const float4*)&ws[k][tx * 4];
                float av[4] = {a4.x, a4.y, a4.z, a4.w};
                float bv[4] = {b4.x, b4.y, b4.z, b4.w};
                #pragma unroll
                for (int ri = 0; ri < 4; ri++)
                    #pragma unroll
                    for (int cj = 0; cj < 4; cj++) acc[ri][cj] += av[ri] * bv[cj];
            }
            __syncthreads();
        }
        #pragma unroll
        for (int ri = 0; ri < 4; ri++) {
            int r = r0 + ty * 4 + ri;
            #pragma unroll
            for (int cj = 0; cj < 4; cj++) {
                int c = c0 + tx * 4 + cj;
                uint32_t v = f2tf32(acc[ri][cj] + bkv[c]);
                if (c < HD_) {
                    g_kt[(size_t)r * HD_ + KPERM(c)] = v;
                } else {
                    int d = c - HD_;
                    int bb = r >> 10, n = r & (N_ - 1);
                    g_vtT[((size_t)bb * HD_ + d) * N_ + KPERM(n)] = v;
                }
            }
        }
    }
}

/* ------------------------ zero output (for atomic reduce) ------------------- */
__global__ void zero_out_kernel(float* __restrict__ out, int n) {
    int tid = threadIdx.x;
    float4* o4 = (float4*)out;
    const int n4 = NT * DIM_ / 4;
    for (int i = blockIdx.x * 256 + tid; i < n4; i += 256 * 256)
        o4[i] = make_float4(0.f, 0.f, 0.f, 0.f);
    for (int i = NT * DIM_ + blockIdx.x * 256 + tid; i < n; i += 256 * 256)
        out[i] = 0.f;
}

/* ------- grouped q projection: cp.async dbuf, LDS.64, stride 40 ------------- */
#define QX_STR 40
#define Q_SMEM_WORDS (2*128*QX_STR + 2*96*QX_STR)
__global__ void __launch_bounds__(256) q_tc_kernel() {
    int e = blockIdx.y;
    int count = g_ecount[e];
    int base = blockIdx.x * 128;
    if (base >= count) return;

    extern __shared__ uint32_t qsm[];
    uint32_t* xs = qsm;
    uint32_t* ws = qsm + 2 * 128 * QX_STR;
    __shared__ int s_a[128];
    int tid = threadIdx.x;
    if (tid < 128) {
        int idx = base + tid; if (idx >= count) idx = count - 1;
        s_a[tid] = g_elist[e * NA + idx];
    }
    __syncthreads();

    uint32_t xs_smem = (uint32_t)__cvta_generic_to_shared(xs);
    uint32_t ws_smem = (uint32_t)__cvta_generic_to_shared(ws);
    const uint32_t* w1t = g_w1t + (size_t)e * HD_ * DIM_;

    int wid = tid >> 5, lane = tid & 31;
    int g = lane >> 2, tig = lane & 3;
    int row_a0 = wid * 16 + g, row_a1 = row_a0 + 8;

    float acc[12][4];
    #pragma unroll
    for (int nn = 0; nn < 12; nn++)
        #pragma unroll
        for (int r = 0; r < 4; r++) acc[nn][r] = 0.f;

    auto fill = [&](int bi, int k0) {
        uint32_t xb = xs_smem + bi * (128 * QX_STR * 4);
        uint32_t wb = ws_smem + bi * (96 * QX_STR * 4);
        #pragma unroll
        for (int j = 0; j < 4; j++) {
            int item = tid + 256 * j;
            int r = item >> 3, seg = item & 7;
            int tok = s_a[r] >> 3;
            cp_async16(xb + (r * QX_STR + seg * 4) * 4,
                       g_xt + (size_t)tok * DIM_ + k0 + seg * 4);
        }
        #pragma unroll
        for (int j = 0; j < 3; j++) {
            int item = tid + 256 * j;
            int c = item >> 3, seg = item & 7;
            cp_async16(wb + (c * QX_STR + seg * 4) * 4,
                       w1t + (size_t)c * DIM_ + k0 + seg * 4);
        }
        cp_commit();
    };

    fill(0, 0);
    for (int c = 0; c < 24; c++) {
        if (c < 23) fill((c + 1) & 1, (c + 1) * 32);
        if (c < 23) cp_wait<1>(); else cp_wait<0>();
        __syncthreads();
        uint32_t* xsb = xs + (c & 1) * 128 * QX_STR;
        uint32_t* wsb = ws + (c & 1) * 96 * QX_STR;
        #pragma unroll
        for (int kk = 0; kk < 4; kk++) {
            uint32_t a[4];
            uint2 xa0 = *(const uint2*)&xsb[row_a0 * QX_STR + kk * 8 + 2 * tig];
            uint2 xa1 = *(const uint2*)&xsb[row_a1 * QX_STR + kk * 8 + 2 * tig];
            a[0] = xa0.x; a[2] = xa0.y;
            a[1] = xa1.x; a[3] = xa1.y;
            #pragma unroll
            for (int nn = 0; nn < 12; nn++) {
                uint2 wb_ = *(const uint2*)&wsb[(nn * 8 + g) * QX_STR + kk * 8 + 2 * tig];
                uint32_t bb[2] = {wb_.x, wb_.y};
                mma_tf32(acc[nn], a, bb);
            }
        }
        __syncthreads();
    }

    bool ok0 = (base + row_a0 < count), ok1 = (base + row_a1 < count);
    int a0 = s_a[row_a0], a1 = s_a[row_a1];
    #pragma unroll
    for (int nn = 0; nn < 12; nn++) {
        int c = nn * 8 + tig * 2;
        if (ok0) {
            g_qt[(size_t)a0 * HD_ + KPERM(c)]     = f2tf32(acc[nn][0] * SCALE_);
            g_qt[(size_t)a0 * HD_ + KPERM(c + 1)] = f2tf32(acc[nn][1] * SCALE_);
        }
        if (ok1) {
            g_qt[(size_t)a1 * HD_ + KPERM(c)]     = f2tf32(acc[nn][2] * SCALE_);
            g_qt[(size_t)a1 * HD_ + KPERM(c + 1)] = f2tf32(acc[nn][3] * SCALE_);
        }
    }
}

/* ------- fused flash attention: cp.async dbuf, full LDS.64 ------------------ */
#define QS_STRIDE 104
#define KS_STRIDE 104
#define VS_STRIDE 72
#define PS_STRIDE 72
#define ATTN_SMEM_WORDS (128*QS_STRIDE + 2*64*KS_STRIDE + 2*96*VS_STRIDE + 8*16*PS_STRIDE)

__global__ void __launch_bounds__(256, 1) attn_tc_kernel() {
    extern __shared__ uint32_t smu[];
    uint32_t* qs = smu;                                    /* [128][104]   */
    uint32_t* ks = qs + 128 * QS_STRIDE;                   /* [2][64][104] */
    uint32_t* vs = ks + 2 * 64 * KS_STRIDE;                /* [2][96][72]  */
    uint32_t* ps = vs + 2 * 96 * VS_STRIDE;                /* [8][16][72]  */

    int it = blockIdx.x, bh = blockIdx.y;
    int b = bh >> 3, h = bh & 7;
    int i0 = it * 128;
    int tid  = threadIdx.x;
    int wid  = tid >> 5;
    int lane = tid & 31;
    int g    = lane >> 2;
    int tig  = lane & 3;
    uint32_t* pw = ps + wid * 16 * PS_STRIDE;

    uint32_t qs_s = (uint32_t)__cvta_generic_to_shared(qs);
    uint32_t ks_s = (uint32_t)__cvta_generic_to_shared(ks);
    uint32_t vs_s = (uint32_t)__cvta_generic_to_shared(vs);

    #pragma unroll
    for (int j = 0; j < 12; j++) {
        int item = tid + 256 * j;
        int r = item / 24, seg = item % 24;
        cp_async16(qs_s + (r * QS_STRIDE + seg * 4) * 4,
                   g_qt + ((size_t)(b * N_ + i0 + r) * H_ + h) * HD_ + seg * 4);
    }
    cp_commit();

    auto fill_kv = [&](int bi, int jt) {
        int j0 = jt * 64;
        uint32_t kb = ks_s + bi * (64 * KS_STRIDE * 4);
        uint32_t vb = vs_s + bi * (96 * VS_STRIDE * 4);
        #pragma unroll
        for (int j = 0; j < 6; j++) {          /* K: 64 rows x 24 segs */
            int item = tid + 256 * j;
            int r = item / 24, seg = item % 24;
            cp_async16(kb + (r * KS_STRIDE + seg * 4) * 4,
                       g_kt + (size_t)(b * N_ + j0 + r) * HD_ + seg * 4);
        }
        #pragma unroll
        for (int j = 0; j < 6; j++) {          /* V^T: 96 rows x 16 segs */
            int item = tid + 256 * j;
            int d = item >> 4, seg = item & 15;
            cp_async16(vb + (d * VS_STRIDE + seg * 4) * 4,
                       g_vtT + ((size_t)b * HD_ + d) * N_ + j0 + seg * 4);
        }
        cp_commit();
    };
    fill_kv(0, 0);

    float m0 = -1e30f, m1 = -1e30f, l0 = 0.f, l1 = 0.f;
    float o_acc[12][4];
    #pragma unroll
    for (int nn = 0; nn < 12; nn++)
        #pragma unroll
        for (int r = 0; r < 4; r++) o_acc[nn][r] = 0.f;

    int row_a0 = wid * 16 + g;
    int row_a1 = wid * 16 + g + 8;

    for (int jt = 0; jt < 16; jt++) {
        cp_wait<0>();
        __syncthreads();
        if (jt < 15) fill_kv((jt + 1) & 1, jt + 1);
        uint32_t* ksb = ks + (jt & 1) * 64 * KS_STRIDE;
        uint32_t* vsb = vs + (jt & 1) * 96 * VS_STRIDE;

        float sv[8][4];
        #pragma unroll
        for (int nn = 0; nn < 8; nn++)
            #pragma unroll
            for (int r = 0; r < 4; r++) sv[nn][r] = 0.f;

        #pragma unroll
        for (int kk = 0; kk < 12; kk++) {
            uint32_t a[4];
            uint2 qa0 = *(const uint2*)&qs[row_a0 * QS_STRIDE + kk * 8 + 2 * tig];
            uint2 qa1 = *(const uint2*)&qs[row_a1 * QS_STRIDE + kk * 8 + 2 * tig];
            a[0] = qa0.x; a[2] = qa0.y;
            a[1] = qa1.x; a[3] = qa1.y;
            #pragma unroll
            for (int nn = 0; nn < 8; nn++) {
                uint2 kb_ = *(const uint2*)&ksb[(nn * 8 + g) * KS_STRIDE + kk * 8 + 2 * tig];
                uint32_t bb[2] = {kb_.x, kb_.y};
                mma_tf32(sv[nn], a, bb);
            }
        }

        float rmax0 = -1e30f, rmax1 = -1e30f;
        #pragma unroll
        for (int nn = 0; nn < 8; nn++) {
            rmax0 = fmaxf(rmax0, fmaxf(sv[nn][0], sv[nn][1]));
            rmax1 = fmaxf(rmax1, fmaxf(sv[nn][2], sv[nn][3]));
        }
        #pragma unroll
        for (int o = 1; o <= 2; o <<= 1) {
            rmax0 = fmaxf(rmax0, __shfl_xor_sync(0xffffffffu, rmax0, o));
            rmax1 = fmaxf(rmax1, __shfl_xor_sync(0xffffffffu, rmax1, o));
        }
        float nm0 = fmaxf(m0, rmax0), nm1 = fmaxf(m1, rmax1);
        float corr0 = __expf(m0 - nm0), corr1 = __expf(m1 - nm1);
        float rs0 = 0.f, rs1 = 0.f;
        #pragma unroll
        for (int nn = 0; nn < 8; nn++) {
            float p00 = __expf(sv[nn][0] - nm0);
            float p01 = __expf(sv[nn][1] - nm0);
            float p10 = __expf(sv[nn][2] - nm1);
            float p11 = __expf(sv[nn][3] - nm1);
            rs0 += p00 + p01; rs1 += p10 + p11;
            int c = nn * 8 + tig * 2;
            pw[g * PS_STRIDE + KPERM(c)]           = f2tf32(p00);
            pw[g * PS_STRIDE + KPERM(c + 1)]       = f2tf32(p01);
            pw[(g + 8) * PS_STRIDE + KPERM(c)]     = f2tf32(p10);
            pw[(g + 8) * PS_STRIDE + KPERM(c + 1)] = f2tf32(p11);
        }
        #pragma unroll
        for (int o = 1; o <= 2; o <<= 1) {
            rs0 += __shfl_xor_sync(0xffffffffu, rs0, o);
            rs1 += __shfl_xor_sync(0xffffffffu, rs1, o);
        }
        l0 = l0 * corr0 + rs0;  m0 = nm0;
        l1 = l1 * corr1 + rs1;  m1 = nm1;
        #pragma unroll
        for (int nn = 0; nn < 12; nn++) {
            o_acc[nn][0] *= corr0; o_acc[nn][1] *= corr0;
            o_acc[nn][2] *= corr1; o_acc[nn][3] *= corr1;
        }
        __syncwarp();

        #pragma unroll
        for (int kk = 0; kk < 8; kk++) {
            uint32_t a[4];
            uint2 pa0 = *(const uint2*)&pw[g * PS_STRIDE + kk * 8 + 2 * tig];
            uint2 pa1 = *(const uint2*)&pw[(g + 8) * PS_STRIDE + kk * 8 + 2 * tig];
            a[0] = pa0.x; a[2] = pa0.y;
            a[1] = pa1.x; a[3] = pa1.y;
            #pragma unroll
            for (int nn = 0; nn < 12; nn++) {
                uint2 vb_ = *(const uint2*)&vsb[(nn * 8 + g) * VS_STRIDE + kk * 8 + 2 * tig];
                uint32_t bb[2] = {vb_.x, vb_.y};
                mma_tf32(o_acc[nn], a, bb);
            }
        }
        __syncwarp();
    }

    /* epilogue: gate-weighted tf32 o rows, KPERM'd for the reduce kernel */
    float inv0 = 1.f / l0, inv1 = 1.f / l1;
    int tok0 = b * N_ + i0 + row_a0;
    int tok1 = b * N_ + i0 + row_a1;
    int a0 = tok0 * H_ + h, a1 = tok1 * H_ + h;
    float ga0 = g_gate[a0], ga1 = g_gate[a1];
    #pragma unroll
    for (int nn = 0; nn < 12; nn++) {
        int c = nn * 8 + tig * 2;
        g_ot[(size_t)a0 * HD_ + KPERM(c)]     = f2tf32(ga0 * (o_acc[nn][0] * inv0));
        g_ot[(size_t)a0 * HD_ + KPERM(c + 1)] = f2tf32(ga0 * (o_acc[nn][1] * inv0));
        g_ot[(size_t)a1 * HD_ + KPERM(c)]     = f2tf32(ga1 * (o_acc[nn][2] * inv1));
        g_ot[(size_t)a1 * HD_ + KPERM(c + 1)] = f2tf32(ga1 * (o_acc[nn][3] * inv1));
    }
}

/* -- grouped reduce (R15 form, measured 118.5us): stride 104, LDS.64 --------- */
#define RD_STR 104
#define RED_SMEM_WORDS (128*RD_STR + 2*48*RD_STR)   /* 93184 bytes */
__global__ void __launch_bounds__(256) red_tc_kernel(float* __restrict__ out) {
    int e = blockIdx.y;
    int count = g_ecount[e];
    int base = blockIdx.x * 128;
    if (base >= count) return;

    extern __shared__ uint32_t rsm[];
    uint32_t* osT = rsm;                      /* [128][104]   */
    uint32_t* w2T = rsm + 128 * RD_STR;       /* [2][48][104] */
    __shared__ int s_a[128];

    int tid = threadIdx.x;
    if (tid < 128) {
        int idx = base + tid; if (idx >= count) idx = count - 1;
        s_a[tid] = g_elist[e * NA + idx];
    }
    __syncthreads();

    uint32_t osT_s = (uint32_t)__cvta_generic_to_shared(osT);
    uint32_t w2T_s = (uint32_t)__cvta_generic_to_shared(w2T);
    const uint32_t* w2te = g_w2t + (size_t)e * DIM_ * HD_;

    #pragma unroll
    for (int j = 0; j < 12; j++) {
        int item = tid + 256 * j;
        int r = item / 24, seg = item % 24;
        int a = s_a[r];
        cp_async16(osT_s + (r * RD_STR + seg * 4) * 4,
                   g_ot + (size_t)a * HD_ + seg * 4);
    }

    auto fill_w2 = [&](int bi, int ct) {
        uint32_t wb = w2T_s + bi * (48 * RD_STR * 4);
        const uint32_t* src = w2te + (size_t)(ct * 48) * HD_;
        #pragma unroll
        for (int j = 0; j < 5; j++) {
            int item = tid + 256 * j;
            if (item < 1152) {
                int c = item / 24, seg = item % 24;
                cp_async16(wb + (c * RD_STR + seg * 4) * 4,
                           src + (size_t)c * HD_ + seg * 4);
            }
        }
        cp_commit();
    };
    fill_w2(0, 0);

    int wid = tid >> 5, lane = tid & 31;
    int g = lane >> 2, tig = lane & 3;
    int row_a0 = wid * 16 + g, row_a1 = row_a0 + 8;
    bool ok0 = (base + row_a0 < count), ok1 = (base + row_a1 < count);
    int t0 = s_a[row_a0] >> 3, t1 = s_a[row_a1] >> 3;

    for (int ct = 0; ct < 16; ct++) {
        if (ct < 15) fill_w2((ct + 1) & 1, ct + 1);
        if (ct < 15) cp_wait<1>(); else cp_wait<0>();
        __syncthreads();
        uint32_t* wsb = w2T + (ct & 1) * 48 * RD_STR;

        float acc[6][4];
        #pragma unroll
        for (int nn = 0; nn < 6; nn++)
            #pragma unroll
            for (int r = 0; r < 4; r++) acc[nn][r] = 0.f;

        #pragma unroll
        for (int kk = 0; kk < 12; kk++) {
            uint32_t a[4];
            uint2 oa0 = *(const uint2*)&osT[row_a0 * RD_STR + kk * 8 + 2 * tig];
            uint2 oa1 = *(const uint2*)&osT[row_a1 * RD_STR + kk * 8 + 2 * tig];
            a[0] = oa0.x; a[2] = oa0.y;
            a[1] = oa1.x; a[3] = oa1.y;
            #pragma unroll
            for (int nn = 0; nn < 6; nn++) {
                uint2 wb_ = *(const uint2*)&wsb[(nn * 8 + g) * RD_STR + kk * 8 + 2 * tig];
                uint32_t bb[2] = {wb_.x, wb_.y};
                mma_tf32(acc[nn], a, bb);
            }
        }

        #pragma unroll
        for (int nn = 0; nn < 6; nn++) {
            int c = ct * 48 + nn * 8 + tig * 2;
            if (ok0) red_add_v2(&out[(size_t)t0 * DIM_ + c], acc[nn][0], acc[nn][1]);
            if (ok1) red_add_v2(&out[(size_t)t1 * DIM_ + c], acc[nn][2], acc[nn][3]);
        }
        __syncthreads();
    }
}

/* ------------- aux loss + restore zeroed gating state for next run ---------- */
__global__ void aux_kernel(float* __restrict__ out, int out_size) {
    int tid = threadIdx.x;
    if (tid == 0) {
        float mesum = 0.f;
        for (int e = 0; e < E_; e++) mesum += g_me[e];
        float sw = 0.f;
        for (int e = 0; e < E_; e++)
            sw += (g_me[e] / mesum) * ((float)g_ecount[e] / (float)NA);
        sw *= (float)E_;
        float z = g_z / (float)NT;
        float aux = 0.1f * sw + 0.001f * z;
        if (out_size > NT * DIM_) out[out_size - 1] = aux;
    }
    __syncwarp();
    if (tid < E_) { g_me[tid] = 0.f; g_ecount[tid] = 0; }
    if (tid == 0) g_z = 0.f;
}

/* -------------------------------- launch ------------------------------------ */
extern "C" void kernel_launch(void* const* d_in, const int* in_sizes, int n_in,
                              void* d_out, int out_size) {
    const float* x    = (const float*)d_in[0];
    const float* Wg   = (const float*)d_in[1];
    const float* W1   = (const float*)d_in[2];
    const float* W2   = (const float*)d_in[3];
    const float* Wkv  = (const float*)d_in[4];
    const float* bkv  = (const float*)d_in[5];
    const int*   task = (const int*)d_in[6];
    float* out = (float*)d_out;

    cudaFuncSetAttribute(attn_tc_kernel,
                         cudaFuncAttributeMaxDynamicSharedMemorySize,
                         ATTN_SMEM_WORDS * (int)sizeof(uint32_t));
    cudaFuncSetAttribute(red_tc_kernel,
                         cudaFuncAttributeMaxDynamicSharedMemorySize,
                         RED_SMEM_WORDS * (int)sizeof(uint32_t));
    cudaFuncSetAttribute(q_tc_kernel,
                         cudaFuncAttributeMaxDynamicSharedMemorySize,
                         Q_SMEM_WORDS * (int)sizeof(uint32_t));

    prep_kernel<<<1408, 256>>>(x, Wg, W1, W2, Wkv, bkv, task);               /* #1 */
    q_tc_kernel<<<dim3(64, E_), 256, Q_SMEM_WORDS * sizeof(uint32_t)>>>();   /* #2 */
    zero_out_kernel<<<256, 256>>>(out, out_size);                            /* #3 */
    attn_tc_kernel<<<dim3(8, B_ * H_), 256,
                     ATTN_SMEM_WORDS * sizeof(uint32_t)>>>();                /* #4 */
    red_tc_kernel<<<dim3(64, E_), 256,
                    RED_SMEM_WORDS * sizeof(uint32_t)>>>(out);               /* #5 */
    aux_kernel<<<1, 32>>>(out, out_size);                                    /* #6 */
}